// round 6
// baseline (speedup 1.0000x reference)
#include <cuda_runtime.h>

#define Dm 128
#define Hm 256
#define ROWS 16384   /* 16 * 1024 chunks */
#define NTOK 131072  /* 16 * 8192 tokens */
#define EPSf 1e-5f

typedef unsigned long long u64;
typedef unsigned int u32;

// ---- scratch (device globals; no allocation) ----
__device__ float g_local[NTOK * Dm];   // 64 MB
__device__ float g_hA[ROWS * Dm];      // 8 MB
__device__ float g_hB[ROWS * Dm];      // 8 MB
__device__ float g_proj[ROWS * Hm];    // 16 MB [row][0:128]=self, [128:256]=nbr
__device__ float g_bcb[ROWS * Dm];     // 8 MB
// packed tf32 weight fragments
__device__ float2 g_w1p[16 * 32 * 32]; // lw1 128x256
__device__ float2 g_w2p[32 * 16 * 32]; // lw2 256x128
__device__ float2 g_hwp[16 * 32 * 32]; // head_w 128x256
// 128x128 mats: [0]=w1self [1]=w1nbr [2]=mw2 [3]=uw1a [4]=uw1b [5]=uw2 [6]=bc_w
__device__ float2 g_mwp[7 * 8192];

// ---- packed f32x2 helpers (scalar path) ----
__device__ __forceinline__ u64 pk2(float x, float y) {
    u64 r; asm("mov.b64 %0, {%1, %2};" : "=l"(r) : "f"(x), "f"(y)); return r;
}
__device__ __forceinline__ u64 dup_f(float a) {
    u64 r; asm("mov.b64 %0, {%1, %1};" : "=l"(r) : "f"(a)); return r;
}
__device__ __forceinline__ void fma2(u64& d, u64 a, u64 b) {
    asm("fma.rn.f32x2 %0, %1, %2, %0;" : "+l"(d) : "l"(a), "l"(b));
}
__device__ __forceinline__ float2 u2f(u64 v) {
    float2 r; asm("mov.b64 {%0, %1}, %2;" : "=f"(r.x), "=f"(r.y) : "l"(v)); return r;
}

// ---- tf32 helpers ----
__device__ __forceinline__ u32 f2tf(float f) {
    u32 r; asm("cvt.rna.tf32.f32 %0, %1;" : "=r"(r) : "f"(f)); return r;
}
__device__ __forceinline__ float f2tff(float f) { return __uint_as_float(f2tf(f)); }

// mma.sync m16n8k8 tf32
__device__ __forceinline__ void mma8(float4& c, const u32 a[4], u32 b0, u32 b1) {
    asm volatile(
        "mma.sync.aligned.m16n8k8.row.col.f32.tf32.tf32.f32 "
        "{%0,%1,%2,%3}, {%4,%5,%6,%7}, {%8,%9}, {%0,%1,%2,%3};"
        : "+f"(c.x), "+f"(c.y), "+f"(c.z), "+f"(c.w)
        : "r"(a[0]), "r"(a[1]), "r"(a[2]), "r"(a[3]), "r"(b0), "r"(b1));
}

template<int STRIDE>
__device__ __forceinline__ void ldA_raw(const float* ap, u32 a[4]) {
    a[0] = __float_as_uint(ap[0]);
    a[1] = __float_as_uint(ap[8 * STRIDE]);
    a[2] = __float_as_uint(ap[4]);
    a[3] = __float_as_uint(ap[8 * STRIDE + 4]);
}
template<int STRIDE>
__device__ __forceinline__ void ldA_cvt(const float* ap, u32 a[4]) {
    a[0] = f2tf(ap[0]);
    a[1] = f2tf(ap[8 * STRIDE]);
    a[2] = f2tf(ap[4]);
    a[3] = f2tf(ap[8 * STRIDE + 4]);
}

__device__ __forceinline__ float wsum(float v) {
#pragma unroll
    for (int o = 16; o; o >>= 1) v += __shfl_xor_sync(0xffffffffu, v, o);
    return v;
}
__device__ __forceinline__ float gelu_f(float x) {
    return 0.5f * x * (1.0f + erff(x * 0.70710678118f));
}

__device__ __forceinline__ float4 ln_f4(float4 h, const float* __restrict__ g,
                                        const float* __restrict__ b, int lane) {
    const float mu = wsum(h.x + h.y + h.z + h.w) * (1.0f / 128.0f);
    const float a0 = h.x - mu, a1 = h.y - mu, a2 = h.z - mu, a3 = h.w - mu;
    const float var = wsum(a0 * a0 + a1 * a1 + a2 * a2 + a3 * a3) * (1.0f / 128.0f);
    const float rs = rsqrtf(var + EPSf);
    const int dd = lane * 4;
    const float4 gg = *(const float4*)(g + dd);
    const float4 bb = *(const float4*)(b + dd);
    return make_float4(a0 * rs * gg.x + bb.x, a1 * rs * gg.y + bb.y,
                       a2 * rs * gg.z + bb.z, a3 * rs * gg.w + bb.w);
}

// ---- scalar register-tiled GEMM accumulate (pool only) ----
template<int KDIM, int RPT, int NCP>
__device__ __forceinline__ void mm_acc(const float* __restrict__ s,
                                       const float* __restrict__ W, const int ldw,
                                       u64 acc[RPT][NCP]) {
#pragma unroll 2
    for (int d = 0; d < KDIM; d += 2) {
        u64 w0[NCP], w1[NCP];
        if constexpr (NCP >= 2) {
#pragma unroll
            for (int c = 0; c < NCP; c += 2) {
                const ulonglong2 t0 = *(const ulonglong2*)(W + d * ldw + c * 2);
                const ulonglong2 t1 = *(const ulonglong2*)(W + (d + 1) * ldw + c * 2);
                w0[c] = t0.x; w0[c + 1] = t0.y;
                w1[c] = t1.x; w1[c + 1] = t1.y;
            }
        } else {
            w0[0] = *(const u64*)(W + d * ldw);
            w1[0] = *(const u64*)(W + (d + 1) * ldw);
        }
#pragma unroll
        for (int r = 0; r < RPT; ++r) {
            const float2 a = *(const float2*)(s + r * KDIM + d);
            const u64 a0 = dup_f(a.x), a1 = dup_f(a.y);
#pragma unroll
            for (int c = 0; c < NCP; ++c) {
                fma2(acc[r][c], a0, w0[c]);
                fma2(acc[r][c], a1, w1[c]);
            }
        }
    }
}

// ============================================================
// K0: fused pack of all weights into tf32 B-fragment order
// ============================================================
__device__ __forceinline__ void pack_one(const float* __restrict__ W,
                                         float2* __restrict__ P,
                                         int N, int idx) {
    const int lane = idx & 31;
    const int t = idx >> 5;
    const int nt = t % (N / 8);
    const int ks = t / (N / 8);
    const int k = ks * 8 + (lane & 3);
    const int n = nt * 8 + (lane >> 2);
    P[idx] = make_float2(f2tff(W[k * N + n]), f2tff(W[(k + 4) * N + n]));
}

__global__ __launch_bounds__(256) void k_pack_all(
    const float* __restrict__ lw1, const float* __restrict__ lw2,
    const float* __restrict__ hw,  const float* __restrict__ mw1,
    const float* __restrict__ mw2, const float* __restrict__ uw1,
    const float* __restrict__ uw2, const float* __restrict__ bcw)
{
    const int b = blockIdx.x, tid = threadIdx.x;
    if      (b < 64)  pack_one(lw1, g_w1p, 256, b * 256 + tid);
    else if (b < 128) pack_one(lw2, g_w2p, 128, (b - 64) * 256 + tid);
    else if (b < 192) pack_one(hw,  g_hwp, 256, (b - 128) * 256 + tid);
    else if (b < 224) pack_one(mw1,           g_mwp + 0 * 8192, 128, (b - 192) * 256 + tid);
    else if (b < 256) pack_one(mw1 + 16384,   g_mwp + 1 * 8192, 128, (b - 224) * 256 + tid);
    else if (b < 288) pack_one(mw2,           g_mwp + 2 * 8192, 128, (b - 256) * 256 + tid);
    else if (b < 320) pack_one(uw1,           g_mwp + 3 * 8192, 128, (b - 288) * 256 + tid);
    else if (b < 352) pack_one(uw1 + 16384,   g_mwp + 4 * 8192, 128, (b - 320) * 256 + tid);
    else if (b < 384) pack_one(uw2,           g_mwp + 5 * 8192, 128, (b - 352) * 256 + tid);
    else              pack_one(bcw,           g_mwp + 6 * 8192, 128, (b - 384) * 256 + tid);
}

// ============================================================
// K1: local = h + MLP2(LN(h)) + fused pool/summ (tensor-core)
// 32 tokens (=4 chunks)/block, 256 threads, ~50KB dyn smem
// ============================================================
#define SXL 132
#define SHL 260
__global__ __launch_bounds__(256, 3) void k_local(
    const int* __restrict__ x, const float* __restrict__ emb, const float* __restrict__ pos,
    const float* __restrict__ lb1, const float* __restrict__ lb2,
    const float* __restrict__ lng, const float* __restrict__ lnb,
    const float* __restrict__ pw, const float* __restrict__ pb)
{
    extern __shared__ float sm[];
    float* s_x = sm;                // 32 x 132
    float* s_h = sm + 32 * SXL;     // 32 x 260
    const int tid = threadIdx.x, wid = tid >> 5, lane = tid & 31;
    const int gt0 = blockIdx.x * 32;
    const int frow = lane >> 2, fcol = lane & 3;
    const int mrow = (wid >> 2) * 16, ng = wid & 3;

    // phase 1: LN per token -> tf32 in s_x (4 tokens/warp)
#pragma unroll
    for (int tt = 0; tt < 4; ++tt) {
        const int tl = wid * 4 + tt, gt = gt0 + tl;
        const int xt = __ldg(x + gt);
        const float4 e = *(const float4*)(emb + xt * Dm + lane * 4);
        const float4 p = *(const float4*)(pos + (gt & 7) * Dm + lane * 4);
        const float4 h = make_float4(e.x + p.x, e.y + p.y, e.z + p.z, e.w + p.w);
        const float4 v = ln_f4(h, lng, lnb, lane);
        float* dst = s_x + tl * SXL + lane * 4;
        dst[0] = f2tff(v.x); dst[1] = f2tff(v.y); dst[2] = f2tff(v.z); dst[3] = f2tff(v.w);
    }
    __syncthreads();

    // phase 2: hid = gelu(xln @ lw1 + b1) -> tf32 in s_h (warp: 16 rows x 64 cols)
    {
        float4 acc[8];
#pragma unroll
        for (int nt = 0; nt < 8; ++nt) {
            const int gc = ng * 64 + nt * 8 + 2 * fcol;
            acc[nt] = make_float4(lb1[gc], lb1[gc + 1], lb1[gc], lb1[gc + 1]);
        }
#pragma unroll 4
        for (int ks = 0; ks < 16; ++ks) {
            u32 a[4];
            ldA_raw<SXL>(s_x + (mrow + frow) * SXL + ks * 8 + fcol, a);
#pragma unroll
            for (int nt = 0; nt < 8; ++nt) {
                const float2 b = g_w1p[(ks * 32 + ng * 8 + nt) * 32 + lane];
                mma8(acc[nt], a, __float_as_uint(b.x), __float_as_uint(b.y));
            }
        }
        const int rg = mrow + frow;
#pragma unroll
        for (int nt = 0; nt < 8; ++nt) {
            const int gc = ng * 64 + nt * 8 + 2 * fcol;
            *(float2*)(s_h + rg * SHL + gc) =
                make_float2(f2tff(gelu_f(acc[nt].x)), f2tff(gelu_f(acc[nt].y)));
            *(float2*)(s_h + (rg + 8) * SHL + gc) =
                make_float2(f2tff(gelu_f(acc[nt].z)), f2tff(gelu_f(acc[nt].w)));
        }
    }
    __syncthreads();

    // phase 3: local = h + hid @ lw2 + b2 (warp: 16 rows x 32 cols)
    {
        float4 acc[4];
#pragma unroll
        for (int nt = 0; nt < 4; ++nt) {
            const int gc = ng * 32 + nt * 8 + 2 * fcol;
            acc[nt] = make_float4(lb2[gc], lb2[gc + 1], lb2[gc], lb2[gc + 1]);
        }
#pragma unroll 4
        for (int ks = 0; ks < 32; ++ks) {
            u32 a[4];
            ldA_raw<SHL>(s_h + (mrow + frow) * SHL + ks * 8 + fcol, a);
#pragma unroll
            for (int nt = 0; nt < 4; ++nt) {
                const float2 b = g_w2p[(ks * 16 + ng * 4 + nt) * 32 + lane];
                mma8(acc[nt], a, __float_as_uint(b.x), __float_as_uint(b.y));
            }
        }
        __syncthreads();
#pragma unroll
        for (int rr = 0; rr < 2; ++rr) {
            const int tl = mrow + frow + rr * 8;
            const int gt = gt0 + tl;
            const int xt = __ldg(x + gt);
#pragma unroll
            for (int nt = 0; nt < 4; ++nt) {
                const int gc = ng * 32 + nt * 8 + 2 * fcol;
                const float2 e = *(const float2*)(emb + xt * Dm + gc);
                const float2 p = *(const float2*)(pos + (gt & 7) * Dm + gc);
                const float cx = rr ? acc[nt].z : acc[nt].x;
                const float cy = rr ? acc[nt].w : acc[nt].y;
                const float2 o = make_float2(e.x + p.x + cx, e.y + p.y + cy);
                *(float2*)(g_local + gt * Dm + gc) = o;
                *(float2*)(s_x + tl * SXL + gc) = o;
            }
        }
    }
    __syncthreads();

    // phase 4: chunk means (4 chunks) -> s_h[0:512]
#pragma unroll
    for (int it = 0; it < 2; ++it) {
        const int idx = tid + it * 256;
        const int c = idx >> 7, dd = idx & 127;
        float s = 0.f;
#pragma unroll
        for (int t = 0; t < 8; ++t) s += s_x[(c * 8 + t) * SXL + dd];
        s_h[c * 128 + dd] = s * 0.125f;
    }
    __syncthreads();

    // phase 5: summ = mean @ pool_w + pool_b -> g_hA (warps 0-3, one chunk each)
    if (wid < 4) {
        const int j0 = lane * 4;
        u64 acc1[1][2];
        acc1[0][0] = pk2(pb[j0], pb[j0 + 1]);
        acc1[0][1] = pk2(pb[j0 + 2], pb[j0 + 3]);
        mm_acc<128, 1, 2>(s_h + wid * 128, pw + j0, 128, acc1);
        const float2 v0 = u2f(acc1[0][0]), v1 = u2f(acc1[0][1]);
        *(float4*)(g_hA + (blockIdx.x * 4 + wid) * Dm + j0) =
            make_float4(v0.x, v0.y, v1.x, v1.y);
    }
}

// ============================================================
// K2a: proj = [hmsg @ w1s | hmsg @ w1n] -> g_proj (tensor)
// 64 rows/block, grid 256, 256 threads
// ============================================================
__global__ __launch_bounds__(256) void k_mproj(int useA)
{
    const float* __restrict__ hin = useA ? g_hA : g_hB;
    __shared__ float s_in[64 * SXL];
    const int tid = threadIdx.x, wid = tid >> 5, lane = tid & 31;
    const int r0 = blockIdx.x * 64;
    const int frow = lane >> 2, fcol = lane & 3;

#pragma unroll
    for (int it = 0; it < 32; ++it) {
        const int idx = tid + it * 256;
        const int r = idx >> 7, dd = idx & 127;
        s_in[r * SXL + dd] = f2tff(hin[(r0 + r) * Dm + dd]);
    }
    __syncthreads();

    const int mg = (wid & 1) * 32;
    const int grp = wid >> 1;
    const int mat = grp >> 1;
    const int nh = grp & 1;
    const float2* __restrict__ WP = g_mwp + mat * 8192;

    float4 acc[2][8];
#pragma unroll
    for (int mt = 0; mt < 2; ++mt)
#pragma unroll
        for (int nt = 0; nt < 8; ++nt) acc[mt][nt] = make_float4(0.f, 0.f, 0.f, 0.f);

#pragma unroll 4
    for (int ks = 0; ks < 16; ++ks) {
        u32 a[2][4];
#pragma unroll
        for (int mt = 0; mt < 2; ++mt)
            ldA_raw<SXL>(s_in + (mg + mt * 16 + frow) * SXL + ks * 8 + fcol, a[mt]);
#pragma unroll
        for (int nt = 0; nt < 8; ++nt) {
            const float2 b = WP[(ks * 16 + nh * 8 + nt) * 32 + lane];
#pragma unroll
            for (int mt = 0; mt < 2; ++mt)
                mma8(acc[mt][nt], a[mt], __float_as_uint(b.x), __float_as_uint(b.y));
        }
    }

#pragma unroll
    for (int mt = 0; mt < 2; ++mt) {
        const int rg = r0 + mg + mt * 16 + frow;
#pragma unroll
        for (int nt = 0; nt < 8; ++nt) {
            const int gc = mat * 128 + nh * 64 + nt * 8 + 2 * fcol;
            *(float2*)(g_proj + rg * Hm + gc)       = make_float2(acc[mt][nt].x, acc[mt][nt].y);
            *(float2*)(g_proj + (rg + 8) * Hm + gc) = make_float2(acc[mt][nt].z, acc[mt][nt].w);
        }
    }
}

// ============================================================
// K2b: gelu-sum -> agg -> upd MLP -> LN (-> bc on last round)
// 32 rows/block, grid 512, 256 threads, ~50KB dyn smem
// ============================================================
__global__ __launch_bounds__(256, 4) void k_msg2(
    int useA, int last,
    const float* __restrict__ mb1, const float* __restrict__ mb2,
    const float* __restrict__ ub1, const float* __restrict__ ub2,
    const float* __restrict__ lg, const float* __restrict__ lb,
    const float* __restrict__ bcb)
{
    const float* __restrict__ hin = useA ? g_hA : g_hB;
    float* __restrict__ hout = useA ? g_hB : g_hA;
    extern __shared__ float sm[];
    float* s_hm = sm;              // 32x132 fp32 hmsg (later tf32 LN result)
    float* s_hs = sm + 32 * SXL;   // 32x132 tf32 gelu-sum, later uh
    float* s_ag = sm + 64 * SXL;   // 32x132 tf32 agg, later fp32 pre-LN
    const int tid = threadIdx.x, wid = tid >> 5, lane = tid & 31;
    const int r0 = blockIdx.x * 32;
    const int frow = lane >> 2, fcol = lane & 3;
    const int mrow = (wid >> 2) * 16, ng = wid & 3;

    // P0: load hmsg + gelu-sum from g_proj
#pragma unroll
    for (int it = 0; it < 16; ++it) {
        const int idx = tid + it * 256;
        const int r = idx >> 7, j = idx & 127;
        s_hm[r * SXL + j] = hin[(r0 + r) * Dm + j];
        const int row = r0 + r;
        const int i = row & 1023;
        const float ps_b = __ldg(g_proj + row * Hm + j) + mb1[j];
        float a = 0.f;
#pragma unroll
        for (int dd = 0; dd < 5; ++dd) {
            if (i >= dd) a += gelu_f(ps_b + __ldg(g_proj + (row - dd) * Hm + 128 + j));
        }
        s_hs[r * SXL + j] = f2tff(a);
    }
    __syncthreads();

    // P1: agg = (HS @ mw2)/count + b2 -> s_ag (tf32)
    {
        float4 acc[4];
#pragma unroll
        for (int nt = 0; nt < 4; ++nt) acc[nt] = make_float4(0.f, 0.f, 0.f, 0.f);
#pragma unroll 4
        for (int ks = 0; ks < 16; ++ks) {
            u32 a[4];
            ldA_raw<SXL>(s_hs + (mrow + frow) * SXL + ks * 8 + fcol, a);
#pragma unroll
            for (int nt = 0; nt < 4; ++nt) {
                const float2 b = g_mwp[2 * 8192 + (ks * 16 + ng * 4 + nt) * 32 + lane];
                mma8(acc[nt], a, __float_as_uint(b.x), __float_as_uint(b.y));
            }
        }
        __syncthreads();
        const int rA = mrow + frow;
        const int iA = (r0 + rA) & 1023, iB = (r0 + rA + 8) & 1023;
        const float invA = 1.0f / ((iA + 1) < 5 ? (float)(iA + 1) : 5.0f);
        const float invB = 1.0f / ((iB + 1) < 5 ? (float)(iB + 1) : 5.0f);
#pragma unroll
        for (int nt = 0; nt < 4; ++nt) {
            const int gc = ng * 32 + nt * 8 + 2 * fcol;
            const float b20 = mb2[gc], b21 = mb2[gc + 1];
            *(float2*)(s_ag + rA * SXL + gc) =
                make_float2(f2tff(acc[nt].x * invA + b20), f2tff(acc[nt].y * invA + b21));
            *(float2*)(s_ag + (rA + 8) * SXL + gc) =
                make_float2(f2tff(acc[nt].z * invB + b20), f2tff(acc[nt].w * invB + b21));
        }
    }
    __syncthreads();

    // P2: uh = gelu(HM @ uw1a + AG @ uw1b + ub1) -> s_hs (tf32)
    {
        float4 acc[4];
#pragma unroll
        for (int nt = 0; nt < 4; ++nt) {
            const int gc = ng * 32 + nt * 8 + 2 * fcol;
            acc[nt] = make_float4(ub1[gc], ub1[gc + 1], ub1[gc], ub1[gc + 1]);
        }
#pragma unroll 4
        for (int ks = 0; ks < 16; ++ks) {
            u32 a[4];
            ldA_cvt<SXL>(s_hm + (mrow + frow) * SXL + ks * 8 + fcol, a);
#pragma unroll
            for (int nt = 0; nt < 4; ++nt) {
                const float2 b = g_mwp[3 * 8192 + (ks * 16 + ng * 4 + nt) * 32 + lane];
                mma8(acc[nt], a, __float_as_uint(b.x), __float_as_uint(b.y));
            }
        }
#pragma unroll 4
        for (int ks = 0; ks < 16; ++ks) {
            u32 a[4];
            ldA_raw<SXL>(s_ag + (mrow + frow) * SXL + ks * 8 + fcol, a);
#pragma unroll
            for (int nt = 0; nt < 4; ++nt) {
                const float2 b = g_mwp[4 * 8192 + (ks * 16 + ng * 4 + nt) * 32 + lane];
                mma8(acc[nt], a, __float_as_uint(b.x), __float_as_uint(b.y));
            }
        }
        __syncthreads();
        const int rA = mrow + frow;
#pragma unroll
        for (int nt = 0; nt < 4; ++nt) {
            const int gc = ng * 32 + nt * 8 + 2 * fcol;
            *(float2*)(s_hs + rA * SXL + gc) =
                make_float2(f2tff(gelu_f(acc[nt].x)), f2tff(gelu_f(acc[nt].y)));
            *(float2*)(s_hs + (rA + 8) * SXL + gc) =
                make_float2(f2tff(gelu_f(acc[nt].z)), f2tff(gelu_f(acc[nt].w)));
        }
    }
    __syncthreads();

    // P3: pre-LN = hmsg + UH @ uw2 + ub2 -> s_ag (fp32)
    {
        float4 acc[4];
#pragma unroll
        for (int nt = 0; nt < 4; ++nt) {
            const int gc = ng * 32 + nt * 8 + 2 * fcol;
            acc[nt] = make_float4(ub2[gc], ub2[gc + 1], ub2[gc], ub2[gc + 1]);
        }
#pragma unroll 4
        for (int ks = 0; ks < 16; ++ks) {
            u32 a[4];
            ldA_raw<SXL>(s_hs + (mrow + frow) * SXL + ks * 8 + fcol, a);
#pragma unroll
            for (int nt = 0; nt < 4; ++nt) {
                const float2 b = g_mwp[5 * 8192 + (ks * 16 + ng * 4 + nt) * 32 + lane];
                mma8(acc[nt], a, __float_as_uint(b.x), __float_as_uint(b.y));
            }
        }
        __syncthreads();
        const int rA = mrow + frow;
#pragma unroll
        for (int nt = 0; nt < 4; ++nt) {
            const int gc = ng * 32 + nt * 8 + 2 * fcol;
            const float2 h0 = *(const float2*)(s_hm + rA * SXL + gc);
            const float2 h1 = *(const float2*)(s_hm + (rA + 8) * SXL + gc);
            *(float2*)(s_ag + rA * SXL + gc) =
                make_float2(h0.x + acc[nt].x, h0.y + acc[nt].y);
            *(float2*)(s_ag + (rA + 8) * SXL + gc) =
                make_float2(h1.x + acc[nt].z, h1.y + acc[nt].w);
        }
    }
    __syncthreads();

    // P4: LN per row (4 rows/warp). Non-final: -> hout. Final: tf32 -> s_hm.
#pragma unroll
    for (int rr = 0; rr < 4; ++rr) {
        const int r = wid * 4 + rr;
        const float4 v0 = *(const float4*)(s_ag + r * SXL + lane * 4);
        const float4 v = ln_f4(v0, lg, lb, lane);
        if (!last) {
            *(float4*)(hout + (r0 + r) * Dm + lane * 4) = v;
        } else {
            float* dst = s_hm + r * SXL + lane * 4;
            dst[0] = f2tff(v.x); dst[1] = f2tff(v.y);
            dst[2] = f2tff(v.z); dst[3] = f2tff(v.w);
        }
    }

    // P5 (final round only): bc = hmsg_final @ bc_w + bc_b -> g_bcb
    if (last) {
        __syncthreads();
        float4 acc[4];
#pragma unroll
        for (int nt = 0; nt < 4; ++nt) {
            const int gc = ng * 32 + nt * 8 + 2 * fcol;
            acc[nt] = make_float4(bcb[gc], bcb[gc + 1], bcb[gc], bcb[gc + 1]);
        }
#pragma unroll 4
        for (int ks = 0; ks < 16; ++ks) {
            u32 a[4];
            ldA_raw<SXL>(s_hm + (mrow + frow) * SXL + ks * 8 + fcol, a);
#pragma unroll
            for (int nt = 0; nt < 4; ++nt) {
                const float2 b = g_mwp[6 * 8192 + (ks * 16 + ng * 4 + nt) * 32 + lane];
                mma8(acc[nt], a, __float_as_uint(b.x), __float_as_uint(b.y));
            }
        }
        const int rA = r0 + mrow + frow;
#pragma unroll
        for (int nt = 0; nt < 4; ++nt) {
            const int gc = ng * 32 + nt * 8 + 2 * fcol;
            *(float2*)(g_bcb + rA * Dm + gc)       = make_float2(acc[nt].x, acc[nt].y);
            *(float2*)(g_bcb + (rA + 8) * Dm + gc) = make_float2(acc[nt].z, acc[nt].w);
        }
    }
}

// ============================================================
// K5: logits = LN(local + bc) @ head_w (tensor), 32 tok/block
// ============================================================
__global__ __launch_bounds__(256, 3) void k_head(
    const float* __restrict__ lg, const float* __restrict__ lb,
    float* __restrict__ out)
{
    __shared__ float s_x[32 * SXL];
    const int tid = threadIdx.x, wid = tid >> 5, lane = tid & 31;
    const int gt0 = blockIdx.x * 32;
    const int frow = lane >> 2, fcol = lane & 3;
    const int mrow = (wid >> 2) * 16, ng = wid & 3;

#pragma unroll
    for (int tt = 0; tt < 4; ++tt) {
        const int tl = wid * 4 + tt, gt = gt0 + tl;
        const float4 lv = *(const float4*)(g_local + gt * Dm + lane * 4);
        const float4 bv = *(const float4*)(g_bcb + (gt >> 3) * Dm + lane * 4);
        const float4 h = make_float4(lv.x + bv.x, lv.y + bv.y, lv.z + bv.z, lv.w + bv.w);
        const float4 v = ln_f4(h, lg, lb, lane);
        float* dst = s_x + tl * SXL + lane * 4;
        dst[0] = f2tff(v.x); dst[1] = f2tff(v.y); dst[2] = f2tff(v.z); dst[3] = f2tff(v.w);
    }
    __syncthreads();

    float4 acc[8];
#pragma unroll
    for (int nt = 0; nt < 8; ++nt) acc[nt] = make_float4(0.f, 0.f, 0.f, 0.f);

#pragma unroll 4
    for (int ks = 0; ks < 16; ++ks) {
        u32 a[4];
        ldA_raw<SXL>(s_x + (mrow + frow) * SXL + ks * 8 + fcol, a);
#pragma unroll
        for (int nt = 0; nt < 8; ++nt) {
            const float2 b = g_hwp[(ks * 32 + ng * 8 + nt) * 32 + lane];
            mma8(acc[nt], a, __float_as_uint(b.x), __float_as_uint(b.y));
        }
    }

    const int rg = gt0 + mrow + frow;
#pragma unroll
    for (int nt = 0; nt < 8; ++nt) {
        const int gc = ng * 64 + nt * 8 + 2 * fcol;
        *(float2*)(out + rg * Hm + gc)       = make_float2(acc[nt].x, acc[nt].y);
        *(float2*)(out + (rg + 8) * Hm + gc) = make_float2(acc[nt].z, acc[nt].w);
    }
}

// ============================================================
extern "C" void kernel_launch(void* const* d_in, const int* in_sizes, int n_in,
                              void* d_out, int out_size) {
    const int*   x      = (const int*)  d_in[0];
    const float* emb    = (const float*)d_in[1];
    const float* pos    = (const float*)d_in[2];
    const float* lw1    = (const float*)d_in[3];
    const float* lb1    = (const float*)d_in[4];
    const float* lw2    = (const float*)d_in[5];
    const float* lb2    = (const float*)d_in[6];
    const float* lln_g  = (const float*)d_in[7];
    const float* lln_b  = (const float*)d_in[8];
    const float* pool_w = (const float*)d_in[9];
    const float* pool_b = (const float*)d_in[10];
    const float* msg_w1 = (const float*)d_in[11];
    const float* msg_b1 = (const float*)d_in[12];
    const float* msg_w2 = (const float*)d_in[13];
    const float* msg_b2 = (const float*)d_in[14];
    const float* upd_w1 = (const float*)d_in[15];
    const float* upd_b1 = (const float*)d_in[16];
    const float* upd_w2 = (const float*)d_in[17];
    const float* upd_b2 = (const float*)d_in[18];
    const float* mln_g  = (const float*)d_in[19];
    const float* mln_b  = (const float*)d_in[20];
    const float* bc_w   = (const float*)d_in[21];
    const float* bc_b   = (const float*)d_in[22];
    const float* fln_g  = (const float*)d_in[23];
    const float* fln_b  = (const float*)d_in[24];
    const float* head_w = (const float*)d_in[25];
    float* out = (float*)d_out;

    const int SMEM_LOCAL = (32 * SXL + 32 * SHL) * 4;   // 50176 B
    const int SMEM_MSG   = (96 * SXL) * 4;              // 50688 B
    cudaFuncSetAttribute(k_local, cudaFuncAttributeMaxDynamicSharedMemorySize, SMEM_LOCAL);
    cudaFuncSetAttribute(k_msg2,  cudaFuncAttributeMaxDynamicSharedMemorySize, SMEM_MSG);

    k_pack_all<<<416, 256>>>(lw1, lw2, head_w, msg_w1, msg_w2, upd_w1, upd_w2, bc_w);

    k_local<<<NTOK / 32, 256, SMEM_LOCAL>>>(x, emb, pos, lb1, lb2,
                                            lln_g, lln_b, pool_w, pool_b);

    // rounds: A->B, B->A, A->(bc)  (last round writes g_bcb, skips hout)
    for (int r = 0; r < 3; ++r) {
        const int useA = (r % 2 == 0) ? 1 : 0;
        const int last = (r == 2) ? 1 : 0;
        k_mproj<<<ROWS / 64, 256>>>(useA);
        k_msg2<<<ROWS / 32, 256, SMEM_MSG>>>(useA, last, msg_b1, msg_b2,
                                             upd_b1, upd_b2, mln_g, mln_b, bc_b);
    }

    k_head<<<NTOK / 32, 256>>>(fln_g, fln_b, out);
}

// round 7
// speedup vs baseline: 1.3948x; 1.3948x over previous
#include <cuda_runtime.h>

#define Dm 128
#define Hm 256
#define ROWS 16384   /* 16 * 1024 chunks */
#define NTOK 131072  /* 16 * 8192 tokens */
#define EPSf 1e-5f

typedef unsigned long long u64;
typedef unsigned int u32;

// ---- scratch (device globals; no allocation) ----
__device__ float g_local[NTOK * Dm];   // 64 MB
__device__ float g_hA[ROWS * Dm];      // 8 MB
__device__ float g_hB[ROWS * Dm];      // 8 MB
__device__ float g_proj[ROWS * Hm];    // 16 MB [row][0:128]=self, [128:256]=nbr
__device__ float g_bcb[ROWS * Dm];     // 8 MB
// packed tf32 weight fragments
__device__ float2 g_w1p[16 * 32 * 32]; // lw1 128x256
__device__ float2 g_w2p[32 * 16 * 32]; // lw2 256x128
__device__ float2 g_hwp[16 * 32 * 32]; // head_w 128x256
// 128x128 mats: [0]=w1self [1]=w1nbr [2]=mw2 [3]=uw1a [4]=uw1b [5]=uw2 [6]=bc_w
__device__ float2 g_mwp[7 * 8192];

// ---- packed f32x2 helpers (scalar path) ----
__device__ __forceinline__ u64 pk2(float x, float y) {
    u64 r; asm("mov.b64 %0, {%1, %2};" : "=l"(r) : "f"(x), "f"(y)); return r;
}
__device__ __forceinline__ u64 dup_f(float a) {
    u64 r; asm("mov.b64 %0, {%1, %1};" : "=l"(r) : "f"(a)); return r;
}
__device__ __forceinline__ void fma2(u64& d, u64 a, u64 b) {
    asm("fma.rn.f32x2 %0, %1, %2, %0;" : "+l"(d) : "l"(a), "l"(b));
}
__device__ __forceinline__ float2 u2f(u64 v) {
    float2 r; asm("mov.b64 {%0, %1}, %2;" : "=f"(r.x), "=f"(r.y) : "l"(v)); return r;
}

// ---- tf32 helpers ----
__device__ __forceinline__ u32 f2tf(float f) {
    u32 r; asm("cvt.rna.tf32.f32 %0, %1;" : "=r"(r) : "f"(f)); return r;
}
__device__ __forceinline__ float f2tff(float f) { return __uint_as_float(f2tf(f)); }

// mma.sync m16n8k8 tf32
__device__ __forceinline__ void mma8(float4& c, const u32 a[4], u32 b0, u32 b1) {
    asm volatile(
        "mma.sync.aligned.m16n8k8.row.col.f32.tf32.tf32.f32 "
        "{%0,%1,%2,%3}, {%4,%5,%6,%7}, {%8,%9}, {%0,%1,%2,%3};"
        : "+f"(c.x), "+f"(c.y), "+f"(c.z), "+f"(c.w)
        : "r"(a[0]), "r"(a[1]), "r"(a[2]), "r"(a[3]), "r"(b0), "r"(b1));
}

template<int STRIDE>
__device__ __forceinline__ void ldA_raw(const float* ap, u32 a[4]) {
    a[0] = __float_as_uint(ap[0]);
    a[1] = __float_as_uint(ap[8 * STRIDE]);
    a[2] = __float_as_uint(ap[4]);
    a[3] = __float_as_uint(ap[8 * STRIDE + 4]);
}
template<int STRIDE>
__device__ __forceinline__ void ldA_cvt(const float* ap, u32 a[4]) {
    a[0] = f2tf(ap[0]);
    a[1] = f2tf(ap[8 * STRIDE]);
    a[2] = f2tf(ap[4]);
    a[3] = f2tf(ap[8 * STRIDE + 4]);
}

__device__ __forceinline__ float wsum(float v) {
#pragma unroll
    for (int o = 16; o; o >>= 1) v += __shfl_xor_sync(0xffffffffu, v, o);
    return v;
}
__device__ __forceinline__ float gelu_f(float x) {
    return 0.5f * x * (1.0f + erff(x * 0.70710678118f));
}

__device__ __forceinline__ float4 ln_f4(float4 h, const float* __restrict__ g,
                                        const float* __restrict__ b, int lane) {
    const float mu = wsum(h.x + h.y + h.z + h.w) * (1.0f / 128.0f);
    const float a0 = h.x - mu, a1 = h.y - mu, a2 = h.z - mu, a3 = h.w - mu;
    const float var = wsum(a0 * a0 + a1 * a1 + a2 * a2 + a3 * a3) * (1.0f / 128.0f);
    const float rs = rsqrtf(var + EPSf);
    const int dd = lane * 4;
    const float4 gg = *(const float4*)(g + dd);
    const float4 bb = *(const float4*)(b + dd);
    return make_float4(a0 * rs * gg.x + bb.x, a1 * rs * gg.y + bb.y,
                       a2 * rs * gg.z + bb.z, a3 * rs * gg.w + bb.w);
}

// ---- scalar register-tiled GEMM accumulate (pool only) ----
template<int KDIM, int RPT, int NCP>
__device__ __forceinline__ void mm_acc(const float* __restrict__ s,
                                       const float* __restrict__ W, const int ldw,
                                       u64 acc[RPT][NCP]) {
#pragma unroll 2
    for (int d = 0; d < KDIM; d += 2) {
        u64 w0[NCP], w1[NCP];
        if constexpr (NCP >= 2) {
#pragma unroll
            for (int c = 0; c < NCP; c += 2) {
                const ulonglong2 t0 = *(const ulonglong2*)(W + d * ldw + c * 2);
                const ulonglong2 t1 = *(const ulonglong2*)(W + (d + 1) * ldw + c * 2);
                w0[c] = t0.x; w0[c + 1] = t0.y;
                w1[c] = t1.x; w1[c + 1] = t1.y;
            }
        } else {
            w0[0] = *(const u64*)(W + d * ldw);
            w1[0] = *(const u64*)(W + (d + 1) * ldw);
        }
#pragma unroll
        for (int r = 0; r < RPT; ++r) {
            const float2 a = *(const float2*)(s + r * KDIM + d);
            const u64 a0 = dup_f(a.x), a1 = dup_f(a.y);
#pragma unroll
            for (int c = 0; c < NCP; ++c) {
                fma2(acc[r][c], a0, w0[c]);
                fma2(acc[r][c], a1, w1[c]);
            }
        }
    }
}

// ============================================================
// K0: fused pack of all weights into tf32 B-fragment order
// ============================================================
__device__ __forceinline__ void pack_one(const float* __restrict__ W,
                                         float2* __restrict__ P,
                                         int N, int idx) {
    const int lane = idx & 31;
    const int t = idx >> 5;
    const int nt = t % (N / 8);
    const int ks = t / (N / 8);
    const int k = ks * 8 + (lane & 3);
    const int n = nt * 8 + (lane >> 2);
    P[idx] = make_float2(f2tff(W[k * N + n]), f2tff(W[(k + 4) * N + n]));
}

__global__ __launch_bounds__(256) void k_pack_all(
    const float* __restrict__ lw1, const float* __restrict__ lw2,
    const float* __restrict__ hw,  const float* __restrict__ mw1,
    const float* __restrict__ mw2, const float* __restrict__ uw1,
    const float* __restrict__ uw2, const float* __restrict__ bcw)
{
    const int b = blockIdx.x, tid = threadIdx.x;
    if      (b < 64)  pack_one(lw1, g_w1p, 256, b * 256 + tid);
    else if (b < 128) pack_one(lw2, g_w2p, 128, (b - 64) * 256 + tid);
    else if (b < 192) pack_one(hw,  g_hwp, 256, (b - 128) * 256 + tid);
    else if (b < 224) pack_one(mw1,           g_mwp + 0 * 8192, 128, (b - 192) * 256 + tid);
    else if (b < 256) pack_one(mw1 + 16384,   g_mwp + 1 * 8192, 128, (b - 224) * 256 + tid);
    else if (b < 288) pack_one(mw2,           g_mwp + 2 * 8192, 128, (b - 256) * 256 + tid);
    else if (b < 320) pack_one(uw1,           g_mwp + 3 * 8192, 128, (b - 288) * 256 + tid);
    else if (b < 352) pack_one(uw1 + 16384,   g_mwp + 4 * 8192, 128, (b - 320) * 256 + tid);
    else if (b < 384) pack_one(uw2,           g_mwp + 5 * 8192, 128, (b - 352) * 256 + tid);
    else              pack_one(bcw,           g_mwp + 6 * 8192, 128, (b - 384) * 256 + tid);
}

// ============================================================
// K1: local = h + MLP2(LN(h)) + fused pool/summ (tensor-core)
// 64 tokens (=8 chunks)/block, 256 threads, ~98KB dyn smem
// ============================================================
#define SXL 132
#define SHL 260
__global__ __launch_bounds__(256) void k_local(
    const int* __restrict__ x, const float* __restrict__ emb, const float* __restrict__ pos,
    const float* __restrict__ lb1, const float* __restrict__ lb2,
    const float* __restrict__ lng, const float* __restrict__ lnb,
    const float* __restrict__ pw, const float* __restrict__ pb)
{
    extern __shared__ float sm[];
    float* s_x = sm;                // 64 x 132
    float* s_h = sm + 64 * SXL;     // 64 x 260
    const int tid = threadIdx.x, wid = tid >> 5, lane = tid & 31;
    const int gt0 = blockIdx.x * 64;
    const int frow = lane >> 2, fcol = lane & 3;

    // phase 1: LN per token -> tf32 in s_x
#pragma unroll
    for (int tt = 0; tt < 8; ++tt) {
        const int tl = wid * 8 + tt, gt = gt0 + tl;
        const int xt = __ldg(x + gt);
        const float4 e = *(const float4*)(emb + xt * Dm + lane * 4);
        const float4 p = *(const float4*)(pos + (gt & 7) * Dm + lane * 4);
        const float4 h = make_float4(e.x + p.x, e.y + p.y, e.z + p.z, e.w + p.w);
        const float4 v = ln_f4(h, lng, lnb, lane);
        float* dst = s_x + tl * SXL + lane * 4;
        dst[0] = f2tff(v.x); dst[1] = f2tff(v.y); dst[2] = f2tff(v.z); dst[3] = f2tff(v.w);
    }
    __syncthreads();

    const int mg = (wid >> 2) * 32;   // 2 m-groups of 32 rows
    const int ng = (wid & 3);         // 4 n-groups

    // phase 2: hid = gelu(xln @ lw1 + b1) -> tf32 in s_h (cols ng*64..+63)
    {
        float4 acc[2][8];
#pragma unroll
        for (int nt = 0; nt < 8; ++nt) {
            const int gc = ng * 64 + nt * 8 + 2 * fcol;
            const float b0 = lb1[gc], b1v = lb1[gc + 1];
#pragma unroll
            for (int mt = 0; mt < 2; ++mt) acc[mt][nt] = make_float4(b0, b1v, b0, b1v);
        }
#pragma unroll 4
        for (int ks = 0; ks < 16; ++ks) {
            u32 a[2][4];
#pragma unroll
            for (int mt = 0; mt < 2; ++mt)
                ldA_raw<SXL>(s_x + (mg + mt * 16 + frow) * SXL + ks * 8 + fcol, a[mt]);
#pragma unroll
            for (int nt = 0; nt < 8; ++nt) {
                const float2 b = g_w1p[(ks * 32 + ng * 8 + nt) * 32 + lane];
#pragma unroll
                for (int mt = 0; mt < 2; ++mt)
                    mma8(acc[mt][nt], a[mt], __float_as_uint(b.x), __float_as_uint(b.y));
            }
        }
#pragma unroll
        for (int mt = 0; mt < 2; ++mt) {
            const int rg = mg + mt * 16 + frow;
#pragma unroll
            for (int nt = 0; nt < 8; ++nt) {
                const int gc = ng * 64 + nt * 8 + 2 * fcol;
                *(float2*)(s_h + rg * SHL + gc) =
                    make_float2(f2tff(gelu_f(acc[mt][nt].x)), f2tff(gelu_f(acc[mt][nt].y)));
                *(float2*)(s_h + (rg + 8) * SHL + gc) =
                    make_float2(f2tff(gelu_f(acc[mt][nt].z)), f2tff(gelu_f(acc[mt][nt].w)));
            }
        }
    }
    __syncthreads();

    // phase 3: local = h + hid @ lw2 + b2 -> g_local and s_x (fp32)
    {
        float4 acc[2][4];
#pragma unroll
        for (int nt = 0; nt < 4; ++nt) {
            const int gc = ng * 32 + nt * 8 + 2 * fcol;
            const float b0 = lb2[gc], b1v = lb2[gc + 1];
#pragma unroll
            for (int mt = 0; mt < 2; ++mt) acc[mt][nt] = make_float4(b0, b1v, b0, b1v);
        }
#pragma unroll 4
        for (int ks = 0; ks < 32; ++ks) {
            u32 a[2][4];
#pragma unroll
            for (int mt = 0; mt < 2; ++mt)
                ldA_raw<SHL>(s_h + (mg + mt * 16 + frow) * SHL + ks * 8 + fcol, a[mt]);
#pragma unroll
            for (int nt = 0; nt < 4; ++nt) {
                const float2 b = g_w2p[(ks * 16 + ng * 4 + nt) * 32 + lane];
#pragma unroll
                for (int mt = 0; mt < 2; ++mt)
                    mma8(acc[mt][nt], a[mt], __float_as_uint(b.x), __float_as_uint(b.y));
            }
        }
#pragma unroll
        for (int mt = 0; mt < 2; ++mt) {
#pragma unroll
            for (int rr = 0; rr < 2; ++rr) {
                const int tl = mg + mt * 16 + frow + rr * 8;
                const int gt = gt0 + tl;
                const int xt = __ldg(x + gt);
#pragma unroll
                for (int nt = 0; nt < 4; ++nt) {
                    const int gc = ng * 32 + nt * 8 + 2 * fcol;
                    const float2 e = *(const float2*)(emb + xt * Dm + gc);
                    const float2 p = *(const float2*)(pos + (gt & 7) * Dm + gc);
                    const float cx = rr ? acc[mt][nt].z : acc[mt][nt].x;
                    const float cy = rr ? acc[mt][nt].w : acc[mt][nt].y;
                    const float2 o = make_float2(e.x + p.x + cx, e.y + p.y + cy);
                    *(float2*)(g_local + gt * Dm + gc) = o;
                    *(float2*)(s_x + tl * SXL + gc) = o;
                }
            }
        }
    }
    __syncthreads();

    // phase 4: chunk means (8 chunks) -> s_h[0:1024]
#pragma unroll
    for (int it = 0; it < 4; ++it) {
        const int idx = tid + it * 256;
        const int c = idx >> 7, dd = idx & 127;
        float s = 0.f;
#pragma unroll
        for (int t = 0; t < 8; ++t) s += s_x[(c * 8 + t) * SXL + dd];
        s_h[c * 128 + dd] = s * 0.125f;
    }
    __syncthreads();

    // phase 5: summ = mean @ pool_w + pool_b -> g_hA (warp per chunk)
    {
        const int j0 = lane * 4;
        u64 acc1[1][2];
        acc1[0][0] = pk2(pb[j0], pb[j0 + 1]);
        acc1[0][1] = pk2(pb[j0 + 2], pb[j0 + 3]);
        mm_acc<128, 1, 2>(s_h + wid * 128, pw + j0, 128, acc1);
        const float2 v0 = u2f(acc1[0][0]), v1 = u2f(acc1[0][1]);
        *(float4*)(g_hA + (blockIdx.x * 8 + wid) * Dm + j0) =
            make_float4(v0.x, v0.y, v1.x, v1.y);
    }
}

// ============================================================
// K2a: proj = [hmsg @ w1s | hmsg @ w1n] -> g_proj (tensor)
// 64 rows/block, grid 256, 256 threads
// ============================================================
__global__ __launch_bounds__(256) void k_mproj(int useA)
{
    const float* __restrict__ hin = useA ? g_hA : g_hB;
    __shared__ float s_in[64 * SXL];
    const int tid = threadIdx.x, wid = tid >> 5, lane = tid & 31;
    const int r0 = blockIdx.x * 64;
    const int frow = lane >> 2, fcol = lane & 3;

#pragma unroll
    for (int it = 0; it < 32; ++it) {
        const int idx = tid + it * 256;
        const int r = idx >> 7, dd = idx & 127;
        s_in[r * SXL + dd] = f2tff(hin[(r0 + r) * Dm + dd]);
    }
    __syncthreads();

    const int mg = (wid & 1) * 32;        // 2 m-groups of 32 rows
    const int grp = wid >> 1;             // 0..3
    const int mat = grp >> 1;             // 0=self, 1=nbr
    const int nh = grp & 1;               // col half (64 cols)
    const float2* __restrict__ WP = g_mwp + mat * 8192;

    float4 acc[2][8];
#pragma unroll
    for (int mt = 0; mt < 2; ++mt)
#pragma unroll
        for (int nt = 0; nt < 8; ++nt) acc[mt][nt] = make_float4(0.f, 0.f, 0.f, 0.f);

#pragma unroll 4
    for (int ks = 0; ks < 16; ++ks) {
        u32 a[2][4];
#pragma unroll
        for (int mt = 0; mt < 2; ++mt)
            ldA_raw<SXL>(s_in + (mg + mt * 16 + frow) * SXL + ks * 8 + fcol, a[mt]);
#pragma unroll
        for (int nt = 0; nt < 8; ++nt) {
            const float2 b = WP[(ks * 16 + nh * 8 + nt) * 32 + lane];
#pragma unroll
            for (int mt = 0; mt < 2; ++mt)
                mma8(acc[mt][nt], a[mt], __float_as_uint(b.x), __float_as_uint(b.y));
        }
    }

#pragma unroll
    for (int mt = 0; mt < 2; ++mt) {
        const int rg = r0 + mg + mt * 16 + frow;
#pragma unroll
        for (int nt = 0; nt < 8; ++nt) {
            const int gc = mat * 128 + nh * 64 + nt * 8 + 2 * fcol;
            *(float2*)(g_proj + rg * Hm + gc)       = make_float2(acc[mt][nt].x, acc[mt][nt].y);
            *(float2*)(g_proj + (rg + 8) * Hm + gc) = make_float2(acc[mt][nt].z, acc[mt][nt].w);
        }
    }
}

// ============================================================
// K2b: gelu-sum -> agg -> upd MLP -> LN (-> bc on last round)
// 64 rows/block, grid 256, 256 threads, ~99KB dyn smem
// ============================================================
__global__ __launch_bounds__(256) void k_msg2(
    int useA, int last,
    const float* __restrict__ mb1, const float* __restrict__ mb2,
    const float* __restrict__ ub1, const float* __restrict__ ub2,
    const float* __restrict__ lg, const float* __restrict__ lb,
    const float* __restrict__ bcb)
{
    const float* __restrict__ hin = useA ? g_hA : g_hB;
    float* __restrict__ hout = useA ? g_hB : g_hA;
    extern __shared__ float sm[];
    float* s_hm = sm;              // 64x132 fp32 hmsg (last round: tf32 LN result)
    float* s_hs = sm + 64 * SXL;   // 64x132 tf32 gelu-sum, later uh
    float* s_ag = sm + 128 * SXL;  // 64x132 tf32 agg, later fp32 pre-LN
    const int tid = threadIdx.x, wid = tid >> 5, lane = tid & 31;
    const int r0 = blockIdx.x * 64;
    const int frow = lane >> 2, fcol = lane & 3;

    // P0: load hmsg + gelu-sum from g_proj
#pragma unroll
    for (int it = 0; it < 32; ++it) {
        const int idx = tid + it * 256;
        const int r = idx >> 7, j = idx & 127;
        s_hm[r * SXL + j] = hin[(r0 + r) * Dm + j];
        const int row = r0 + r;
        const int i = row & 1023;
        const float ps_b = __ldg(g_proj + row * Hm + j) + mb1[j];
        float a = 0.f;
#pragma unroll
        for (int dd = 0; dd < 5; ++dd) {
            if (i >= dd) a += gelu_f(ps_b + __ldg(g_proj + (row - dd) * Hm + 128 + j));
        }
        s_hs[r * SXL + j] = f2tff(a);
    }
    __syncthreads();

    const int mg = (wid >> 2) * 32;
    const int ng = (wid & 3);

    // P1: agg = (HS @ mw2)/count + b2 -> s_ag (tf32)
    {
        float4 acc[2][4];
#pragma unroll
        for (int mt = 0; mt < 2; ++mt)
#pragma unroll
            for (int nt = 0; nt < 4; ++nt) acc[mt][nt] = make_float4(0.f, 0.f, 0.f, 0.f);
#pragma unroll 4
        for (int ks = 0; ks < 16; ++ks) {
            u32 a[2][4];
#pragma unroll
            for (int mt = 0; mt < 2; ++mt)
                ldA_raw<SXL>(s_hs + (mg + mt * 16 + frow) * SXL + ks * 8 + fcol, a[mt]);
#pragma unroll
            for (int nt = 0; nt < 4; ++nt) {
                const float2 b = g_mwp[2 * 8192 + (ks * 16 + ng * 4 + nt) * 32 + lane];
#pragma unroll
                for (int mt = 0; mt < 2; ++mt)
                    mma8(acc[mt][nt], a[mt], __float_as_uint(b.x), __float_as_uint(b.y));
            }
        }
        __syncthreads();
#pragma unroll
        for (int mt = 0; mt < 2; ++mt) {
            const int rA = mg + mt * 16 + frow;
            const int iA = (r0 + rA) & 1023, iB = (r0 + rA + 8) & 1023;
            const float invA = 1.0f / ((iA + 1) < 5 ? (float)(iA + 1) : 5.0f);
            const float invB = 1.0f / ((iB + 1) < 5 ? (float)(iB + 1) : 5.0f);
#pragma unroll
            for (int nt = 0; nt < 4; ++nt) {
                const int gc = ng * 32 + nt * 8 + 2 * fcol;
                const float b20 = mb2[gc], b21 = mb2[gc + 1];
                *(float2*)(s_ag + rA * SXL + gc) =
                    make_float2(f2tff(acc[mt][nt].x * invA + b20),
                                f2tff(acc[mt][nt].y * invA + b21));
                *(float2*)(s_ag + (rA + 8) * SXL + gc) =
                    make_float2(f2tff(acc[mt][nt].z * invB + b20),
                                f2tff(acc[mt][nt].w * invB + b21));
            }
        }
    }
    __syncthreads();

    // P2: uh = gelu(HM @ uw1a + AG @ uw1b + ub1) -> s_hs (tf32)
    {
        float4 acc[2][4];
#pragma unroll
        for (int nt = 0; nt < 4; ++nt) {
            const int gc = ng * 32 + nt * 8 + 2 * fcol;
            const float b0 = ub1[gc], b1v = ub1[gc + 1];
#pragma unroll
            for (int mt = 0; mt < 2; ++mt) acc[mt][nt] = make_float4(b0, b1v, b0, b1v);
        }
#pragma unroll 4
        for (int ks = 0; ks < 16; ++ks) {
            u32 a[2][4];
#pragma unroll
            for (int mt = 0; mt < 2; ++mt)
                ldA_cvt<SXL>(s_hm + (mg + mt * 16 + frow) * SXL + ks * 8 + fcol, a[mt]);
#pragma unroll
            for (int nt = 0; nt < 4; ++nt) {
                const float2 b = g_mwp[3 * 8192 + (ks * 16 + ng * 4 + nt) * 32 + lane];
#pragma unroll
                for (int mt = 0; mt < 2; ++mt)
                    mma8(acc[mt][nt], a[mt], __float_as_uint(b.x), __float_as_uint(b.y));
            }
        }
#pragma unroll 4
        for (int ks = 0; ks < 16; ++ks) {
            u32 a[2][4];
#pragma unroll
            for (int mt = 0; mt < 2; ++mt)
                ldA_raw<SXL>(s_ag + (mg + mt * 16 + frow) * SXL + ks * 8 + fcol, a[mt]);
#pragma unroll
            for (int nt = 0; nt < 4; ++nt) {
                const float2 b = g_mwp[4 * 8192 + (ks * 16 + ng * 4 + nt) * 32 + lane];
#pragma unroll
                for (int mt = 0; mt < 2; ++mt)
                    mma8(acc[mt][nt], a[mt], __float_as_uint(b.x), __float_as_uint(b.y));
            }
        }
        __syncthreads();
#pragma unroll
        for (int mt = 0; mt < 2; ++mt) {
            const int rA = mg + mt * 16 + frow;
#pragma unroll
            for (int nt = 0; nt < 4; ++nt) {
                const int gc = ng * 32 + nt * 8 + 2 * fcol;
                *(float2*)(s_hs + rA * SXL + gc) =
                    make_float2(f2tff(gelu_f(acc[mt][nt].x)), f2tff(gelu_f(acc[mt][nt].y)));
                *(float2*)(s_hs + (rA + 8) * SXL + gc) =
                    make_float2(f2tff(gelu_f(acc[mt][nt].z)), f2tff(gelu_f(acc[mt][nt].w)));
            }
        }
    }
    __syncthreads();

    // P3: pre-LN = hmsg + UH @ uw2 + ub2 -> s_ag (fp32)
    {
        float4 acc[2][4];
#pragma unroll
        for (int nt = 0; nt < 4; ++nt) {
            const int gc = ng * 32 + nt * 8 + 2 * fcol;
            const float b0 = ub2[gc], b1v = ub2[gc + 1];
#pragma unroll
            for (int mt = 0; mt < 2; ++mt) acc[mt][nt] = make_float4(b0, b1v, b0, b1v);
        }
#pragma unroll 4
        for (int ks = 0; ks < 16; ++ks) {
            u32 a[2][4];
#pragma unroll
            for (int mt = 0; mt < 2; ++mt)
                ldA_raw<SXL>(s_hs + (mg + mt * 16 + frow) * SXL + ks * 8 + fcol, a[mt]);
#pragma unroll
            for (int nt = 0; nt < 4; ++nt) {
                const float2 b = g_mwp[5 * 8192 + (ks * 16 + ng * 4 + nt) * 32 + lane];
#pragma unroll
                for (int mt = 0; mt < 2; ++mt)
                    mma8(acc[mt][nt], a[mt], __float_as_uint(b.x), __float_as_uint(b.y));
            }
        }
        __syncthreads();
#pragma unroll
        for (int mt = 0; mt < 2; ++mt) {
            const int rA = mg + mt * 16 + frow;
#pragma unroll
            for (int nt = 0; nt < 4; ++nt) {
                const int gc = ng * 32 + nt * 8 + 2 * fcol;
                const float2 h0 = *(const float2*)(s_hm + rA * SXL + gc);
                const float2 h1 = *(const float2*)(s_hm + (rA + 8) * SXL + gc);
                *(float2*)(s_ag + rA * SXL + gc) =
                    make_float2(h0.x + acc[mt][nt].x, h0.y + acc[mt][nt].y);
                *(float2*)(s_ag + (rA + 8) * SXL + gc) =
                    make_float2(h1.x + acc[mt][nt].z, h1.y + acc[mt][nt].w);
            }
        }
    }
    __syncthreads();

    // P4: LN per row. Non-final: -> hout. Final: tf32 -> s_hm.
#pragma unroll
    for (int rr = 0; rr < 8; ++rr) {
        const int r = wid * 8 + rr;
        const float4 v0 = *(const float4*)(s_ag + r * SXL + lane * 4);
        const float4 v = ln_f4(v0, lg, lb, lane);
        if (!last) {
            *(float4*)(hout + (r0 + r) * Dm + lane * 4) = v;
        } else {
            float* dst = s_hm + r * SXL + lane * 4;
            dst[0] = f2tff(v.x); dst[1] = f2tff(v.y);
            dst[2] = f2tff(v.z); dst[3] = f2tff(v.w);
        }
    }

    // P5 (final round only): bc = hmsg_final @ bc_w + bc_b -> g_bcb
    if (last) {
        __syncthreads();
        float4 acc[2][4];
#pragma unroll
        for (int nt = 0; nt < 4; ++nt) {
            const int gc = ng * 32 + nt * 8 + 2 * fcol;
            const float b0 = bcb[gc], b1v = bcb[gc + 1];
#pragma unroll
            for (int mt = 0; mt < 2; ++mt) acc[mt][nt] = make_float4(b0, b1v, b0, b1v);
        }
#pragma unroll 4
        for (int ks = 0; ks < 16; ++ks) {
            u32 a[2][4];
#pragma unroll
            for (int mt = 0; mt < 2; ++mt)
                ldA_raw<SXL>(s_hm + (mg + mt * 16 + frow) * SXL + ks * 8 + fcol, a[mt]);
#pragma unroll
            for (int nt = 0; nt < 4; ++nt) {
                const float2 b = g_mwp[6 * 8192 + (ks * 16 + ng * 4 + nt) * 32 + lane];
#pragma unroll
                for (int mt = 0; mt < 2; ++mt)
                    mma8(acc[mt][nt], a[mt], __float_as_uint(b.x), __float_as_uint(b.y));
            }
        }
#pragma unroll
        for (int mt = 0; mt < 2; ++mt) {
            const int rA = r0 + mg + mt * 16 + frow;
#pragma unroll
            for (int nt = 0; nt < 4; ++nt) {
                const int gc = ng * 32 + nt * 8 + 2 * fcol;
                *(float2*)(g_bcb + rA * Dm + gc)       = make_float2(acc[mt][nt].x, acc[mt][nt].y);
                *(float2*)(g_bcb + (rA + 8) * Dm + gc) = make_float2(acc[mt][nt].z, acc[mt][nt].w);
            }
        }
    }
}

// ============================================================
// K5: logits = LN(local + bc) @ head_w (tensor), 64 tok/block
// ============================================================
__global__ __launch_bounds__(256) void k_head(
    const float* __restrict__ lg, const float* __restrict__ lb,
    float* __restrict__ out)
{
    __shared__ float s_x[64 * SXL];
    const int tid = threadIdx.x, wid = tid >> 5, lane = tid & 31;
    const int gt0 = blockIdx.x * 64;
    const int frow = lane >> 2, fcol = lane & 3;

#pragma unroll
    for (int tt = 0; tt < 8; ++tt) {
        const int tl = wid * 8 + tt, gt = gt0 + tl;
        const float4 lv = *(const float4*)(g_local + gt * Dm + lane * 4);
        const float4 bv = *(const float4*)(g_bcb + (gt >> 3) * Dm + lane * 4);
        const float4 h = make_float4(lv.x + bv.x, lv.y + bv.y, lv.z + bv.z, lv.w + bv.w);
        const float4 v = ln_f4(h, lg, lb, lane);
        float* dst = s_x + tl * SXL + lane * 4;
        dst[0] = f2tff(v.x); dst[1] = f2tff(v.y); dst[2] = f2tff(v.z); dst[3] = f2tff(v.w);
    }
    __syncthreads();

    const int mg = (wid >> 2) * 32;
    const int ng = (wid & 3);
    float4 acc[2][8];
#pragma unroll
    for (int mt = 0; mt < 2; ++mt)
#pragma unroll
        for (int nt = 0; nt < 8; ++nt) acc[mt][nt] = make_float4(0.f, 0.f, 0.f, 0.f);

#pragma unroll 4
    for (int ks = 0; ks < 16; ++ks) {
        u32 a[2][4];
#pragma unroll
        for (int mt = 0; mt < 2; ++mt)
            ldA_raw<SXL>(s_x + (mg + mt * 16 + frow) * SXL + ks * 8 + fcol, a[mt]);
#pragma unroll
        for (int nt = 0; nt < 8; ++nt) {
            const float2 b = g_hwp[(ks * 32 + ng * 8 + nt) * 32 + lane];
#pragma unroll
            for (int mt = 0; mt < 2; ++mt)
                mma8(acc[mt][nt], a[mt], __float_as_uint(b.x), __float_as_uint(b.y));
        }
    }

#pragma unroll
    for (int mt = 0; mt < 2; ++mt) {
        const int rg = gt0 + mg + mt * 16 + frow;
#pragma unroll
        for (int nt = 0; nt < 8; ++nt) {
            const int gc = ng * 64 + nt * 8 + 2 * fcol;
            *(float2*)(out + rg * Hm + gc)       = make_float2(acc[mt][nt].x, acc[mt][nt].y);
            *(float2*)(out + (rg + 8) * Hm + gc) = make_float2(acc[mt][nt].z, acc[mt][nt].w);
        }
    }
}

// ============================================================
extern "C" void kernel_launch(void* const* d_in, const int* in_sizes, int n_in,
                              void* d_out, int out_size) {
    const int*   x      = (const int*)  d_in[0];
    const float* emb    = (const float*)d_in[1];
    const float* pos    = (const float*)d_in[2];
    const float* lw1    = (const float*)d_in[3];
    const float* lb1    = (const float*)d_in[4];
    const float* lw2    = (const float*)d_in[5];
    const float* lb2    = (const float*)d_in[6];
    const float* lln_g  = (const float*)d_in[7];
    const float* lln_b  = (const float*)d_in[8];
    const float* pool_w = (const float*)d_in[9];
    const float* pool_b = (const float*)d_in[10];
    const float* msg_w1 = (const float*)d_in[11];
    const float* msg_b1 = (const float*)d_in[12];
    const float* msg_w2 = (const float*)d_in[13];
    const float* msg_b2 = (const float*)d_in[14];
    const float* upd_w1 = (const float*)d_in[15];
    const float* upd_b1 = (const float*)d_in[16];
    const float* upd_w2 = (const float*)d_in[17];
    const float* upd_b2 = (const float*)d_in[18];
    const float* mln_g  = (const float*)d_in[19];
    const float* mln_b  = (const float*)d_in[20];
    const float* bc_w   = (const float*)d_in[21];
    const float* bc_b   = (const float*)d_in[22];
    const float* fln_g  = (const float*)d_in[23];
    const float* fln_b  = (const float*)d_in[24];
    const float* head_w = (const float*)d_in[25];
    float* out = (float*)d_out;

    const int SMEM_LOCAL = (64 * SXL + 64 * SHL) * 4;   // 100352 B
    const int SMEM_MSG   = (192 * SXL) * 4;             // 101376 B
    cudaFuncSetAttribute(k_local, cudaFuncAttributeMaxDynamicSharedMemorySize, SMEM_LOCAL);
    cudaFuncSetAttribute(k_msg2,  cudaFuncAttributeMaxDynamicSharedMemorySize, SMEM_MSG);

    k_pack_all<<<416, 256>>>(lw1, lw2, head_w, msg_w1, msg_w2, upd_w1, upd_w2, bc_w);

    k_local<<<NTOK / 64, 256, SMEM_LOCAL>>>(x, emb, pos, lb1, lb2,
                                            lln_g, lln_b, pool_w, pool_b);

    // rounds: A->B, B->A, A->(bc)  (last round writes g_bcb, skips hout)
    for (int r = 0; r < 3; ++r) {
        const int useA = (r % 2 == 0) ? 1 : 0;
        const int last = (r == 2) ? 1 : 0;
        k_mproj<<<ROWS / 64, 256>>>(useA);
        k_msg2<<<ROWS / 64, 256, SMEM_MSG>>>(useA, last, msg_b1, msg_b2,
                                             upd_b1, upd_b2, mln_g, mln_b, bc_b);
    }

    k_head<<<NTOK / 64, 256>>>(fln_g, fln_b, out);
}

// round 8
// speedup vs baseline: 1.4579x; 1.0452x over previous
#include <cuda_runtime.h>

#define Dm 128
#define Hm 256
#define ROWS 16384   /* 16 * 1024 chunks */
#define NTOK 131072  /* 16 * 8192 tokens */
#define EPSf 1e-5f

typedef unsigned long long u64;
typedef unsigned int u32;

// ---- scratch (device globals; no allocation) ----
__device__ float g_local[NTOK * Dm];   // 64 MB
__device__ float g_hA[ROWS * Dm];      // 8 MB
__device__ float g_hB[ROWS * Dm];      // 8 MB
__device__ float g_proj[ROWS * Hm];    // 16 MB [row][0:128]=self, [128:256]=nbr
__device__ float g_bcb[ROWS * Dm];     // 8 MB
// packed tf32 weight fragments
__device__ float2 g_w1p[16 * 32 * 32]; // lw1 128x256
__device__ float2 g_w2p[32 * 16 * 32]; // lw2 256x128
__device__ float2 g_hwp[16 * 32 * 32]; // head_w 128x256
// 128x128 mats: [0]=w1self [1]=w1nbr [2]=mw2 [3]=uw1a [4]=uw1b [5]=uw2 [6]=bc_w
__device__ float2 g_mwp[7 * 8192];

// ---- packed f32x2 helpers (scalar path) ----
__device__ __forceinline__ u64 pk2(float x, float y) {
    u64 r; asm("mov.b64 %0, {%1, %2};" : "=l"(r) : "f"(x), "f"(y)); return r;
}
__device__ __forceinline__ u64 dup_f(float a) {
    u64 r; asm("mov.b64 %0, {%1, %1};" : "=l"(r) : "f"(a)); return r;
}
__device__ __forceinline__ void fma2(u64& d, u64 a, u64 b) {
    asm("fma.rn.f32x2 %0, %1, %2, %0;" : "+l"(d) : "l"(a), "l"(b));
}
__device__ __forceinline__ float2 u2f(u64 v) {
    float2 r; asm("mov.b64 {%0, %1}, %2;" : "=f"(r.x), "=f"(r.y) : "l"(v)); return r;
}

// ---- tf32 helpers ----
__device__ __forceinline__ u32 f2tf(float f) {
    u32 r; asm("cvt.rna.tf32.f32 %0, %1;" : "=r"(r) : "f"(f)); return r;
}
__device__ __forceinline__ float f2tff(float f) { return __uint_as_float(f2tf(f)); }

// mma.sync m16n8k8 tf32
__device__ __forceinline__ void mma8(float4& c, const u32 a[4], u32 b0, u32 b1) {
    asm volatile(
        "mma.sync.aligned.m16n8k8.row.col.f32.tf32.tf32.f32 "
        "{%0,%1,%2,%3}, {%4,%5,%6,%7}, {%8,%9}, {%0,%1,%2,%3};"
        : "+f"(c.x), "+f"(c.y), "+f"(c.z), "+f"(c.w)
        : "r"(a[0]), "r"(a[1]), "r"(a[2]), "r"(a[3]), "r"(b0), "r"(b1));
}

template<int STRIDE>
__device__ __forceinline__ void ldA_raw(const float* ap, u32 a[4]) {
    a[0] = __float_as_uint(ap[0]);
    a[1] = __float_as_uint(ap[8 * STRIDE]);
    a[2] = __float_as_uint(ap[4]);
    a[3] = __float_as_uint(ap[8 * STRIDE + 4]);
}
template<int STRIDE>
__device__ __forceinline__ void ldA_cvt(const float* ap, u32 a[4]) {
    a[0] = f2tf(ap[0]);
    a[1] = f2tf(ap[8 * STRIDE]);
    a[2] = f2tf(ap[4]);
    a[3] = f2tf(ap[8 * STRIDE + 4]);
}

__device__ __forceinline__ float wsum(float v) {
#pragma unroll
    for (int o = 16; o; o >>= 1) v += __shfl_xor_sync(0xffffffffu, v, o);
    return v;
}
__device__ __forceinline__ float gelu_f(float x) {
    return 0.5f * x * (1.0f + erff(x * 0.70710678118f));
}

__device__ __forceinline__ float4 ln_f4(float4 h, const float* __restrict__ g,
                                        const float* __restrict__ b, int lane) {
    const float mu = wsum(h.x + h.y + h.z + h.w) * (1.0f / 128.0f);
    const float a0 = h.x - mu, a1 = h.y - mu, a2 = h.z - mu, a3 = h.w - mu;
    const float var = wsum(a0 * a0 + a1 * a1 + a2 * a2 + a3 * a3) * (1.0f / 128.0f);
    const float rs = rsqrtf(var + EPSf);
    const int dd = lane * 4;
    const float4 gg = *(const float4*)(g + dd);
    const float4 bb = *(const float4*)(b + dd);
    return make_float4(a0 * rs * gg.x + bb.x, a1 * rs * gg.y + bb.y,
                       a2 * rs * gg.z + bb.z, a3 * rs * gg.w + bb.w);
}

// ---- scalar register-tiled GEMM accumulate (pool only) ----
template<int KDIM, int RPT, int NCP>
__device__ __forceinline__ void mm_acc(const float* __restrict__ s,
                                       const float* __restrict__ W, const int ldw,
                                       u64 acc[RPT][NCP]) {
#pragma unroll 2
    for (int d = 0; d < KDIM; d += 2) {
        u64 w0[NCP], w1[NCP];
        if constexpr (NCP >= 2) {
#pragma unroll
            for (int c = 0; c < NCP; c += 2) {
                const ulonglong2 t0 = *(const ulonglong2*)(W + d * ldw + c * 2);
                const ulonglong2 t1 = *(const ulonglong2*)(W + (d + 1) * ldw + c * 2);
                w0[c] = t0.x; w0[c + 1] = t0.y;
                w1[c] = t1.x; w1[c + 1] = t1.y;
            }
        } else {
            w0[0] = *(const u64*)(W + d * ldw);
            w1[0] = *(const u64*)(W + (d + 1) * ldw);
        }
#pragma unroll
        for (int r = 0; r < RPT; ++r) {
            const float2 a = *(const float2*)(s + r * KDIM + d);
            const u64 a0 = dup_f(a.x), a1 = dup_f(a.y);
#pragma unroll
            for (int c = 0; c < NCP; ++c) {
                fma2(acc[r][c], a0, w0[c]);
                fma2(acc[r][c], a1, w1[c]);
            }
        }
    }
}

// ============================================================
// K0: fused pack of all weights into tf32 B-fragment order
// ============================================================
__device__ __forceinline__ void pack_one(const float* __restrict__ W,
                                         float2* __restrict__ P,
                                         int N, int idx) {
    const int lane = idx & 31;
    const int t = idx >> 5;
    const int nt = t % (N / 8);
    const int ks = t / (N / 8);
    const int k = ks * 8 + (lane & 3);
    const int n = nt * 8 + (lane >> 2);
    P[idx] = make_float2(f2tff(W[k * N + n]), f2tff(W[(k + 4) * N + n]));
}

__global__ __launch_bounds__(256) void k_pack_all(
    const float* __restrict__ lw1, const float* __restrict__ lw2,
    const float* __restrict__ hw,  const float* __restrict__ mw1,
    const float* __restrict__ mw2, const float* __restrict__ uw1,
    const float* __restrict__ uw2, const float* __restrict__ bcw)
{
    const int b = blockIdx.x, tid = threadIdx.x;
    if      (b < 64)  pack_one(lw1, g_w1p, 256, b * 256 + tid);
    else if (b < 128) pack_one(lw2, g_w2p, 128, (b - 64) * 256 + tid);
    else if (b < 192) pack_one(hw,  g_hwp, 256, (b - 128) * 256 + tid);
    else if (b < 224) pack_one(mw1,           g_mwp + 0 * 8192, 128, (b - 192) * 256 + tid);
    else if (b < 256) pack_one(mw1 + 16384,   g_mwp + 1 * 8192, 128, (b - 224) * 256 + tid);
    else if (b < 288) pack_one(mw2,           g_mwp + 2 * 8192, 128, (b - 256) * 256 + tid);
    else if (b < 320) pack_one(uw1,           g_mwp + 3 * 8192, 128, (b - 288) * 256 + tid);
    else if (b < 352) pack_one(uw1 + 16384,   g_mwp + 4 * 8192, 128, (b - 320) * 256 + tid);
    else if (b < 384) pack_one(uw2,           g_mwp + 5 * 8192, 128, (b - 352) * 256 + tid);
    else              pack_one(bcw,           g_mwp + 6 * 8192, 128, (b - 384) * 256 + tid);
}

// ============================================================
// K1: local = h + MLP2(LN(h)) + fused pool/summ (tensor-core)
// 64 tokens (=8 chunks)/block, 256 threads, ~98KB dyn smem
// ============================================================
#define SXL 132
#define SHL 260
__global__ __launch_bounds__(256, 2) void k_local(
    const int* __restrict__ x, const float* __restrict__ emb, const float* __restrict__ pos,
    const float* __restrict__ lb1, const float* __restrict__ lb2,
    const float* __restrict__ lng, const float* __restrict__ lnb,
    const float* __restrict__ pw, const float* __restrict__ pb)
{
    extern __shared__ float sm[];
    float* s_x = sm;                // 64 x 132
    float* s_h = sm + 64 * SXL;     // 64 x 260
    const int tid = threadIdx.x, wid = tid >> 5, lane = tid & 31;
    const int gt0 = blockIdx.x * 64;
    const int frow = lane >> 2, fcol = lane & 3;

    // phase 1: LN per token -> tf32 in s_x
#pragma unroll
    for (int tt = 0; tt < 8; ++tt) {
        const int tl = wid * 8 + tt, gt = gt0 + tl;
        const int xt = __ldg(x + gt);
        const float4 e = *(const float4*)(emb + xt * Dm + lane * 4);
        const float4 p = *(const float4*)(pos + (gt & 7) * Dm + lane * 4);
        const float4 h = make_float4(e.x + p.x, e.y + p.y, e.z + p.z, e.w + p.w);
        const float4 v = ln_f4(h, lng, lnb, lane);
        float* dst = s_x + tl * SXL + lane * 4;
        dst[0] = f2tff(v.x); dst[1] = f2tff(v.y); dst[2] = f2tff(v.z); dst[3] = f2tff(v.w);
    }
    __syncthreads();

    const int mg = (wid >> 2) * 32;   // 2 m-groups of 32 rows
    const int ng = (wid & 3);         // 4 n-groups

    // phase 2: hid = gelu(xln @ lw1 + b1) -> tf32 in s_h (cols ng*64..+63)
    {
        float4 acc[2][8];
#pragma unroll
        for (int nt = 0; nt < 8; ++nt) {
            const int gc = ng * 64 + nt * 8 + 2 * fcol;
            const float b0 = lb1[gc], b1v = lb1[gc + 1];
#pragma unroll
            for (int mt = 0; mt < 2; ++mt) acc[mt][nt] = make_float4(b0, b1v, b0, b1v);
        }
#pragma unroll 4
        for (int ks = 0; ks < 16; ++ks) {
            u32 a[2][4];
#pragma unroll
            for (int mt = 0; mt < 2; ++mt)
                ldA_raw<SXL>(s_x + (mg + mt * 16 + frow) * SXL + ks * 8 + fcol, a[mt]);
#pragma unroll
            for (int nt = 0; nt < 8; ++nt) {
                const float2 b = g_w1p[(ks * 32 + ng * 8 + nt) * 32 + lane];
#pragma unroll
                for (int mt = 0; mt < 2; ++mt)
                    mma8(acc[mt][nt], a[mt], __float_as_uint(b.x), __float_as_uint(b.y));
            }
        }
#pragma unroll
        for (int mt = 0; mt < 2; ++mt) {
            const int rg = mg + mt * 16 + frow;
#pragma unroll
            for (int nt = 0; nt < 8; ++nt) {
                const int gc = ng * 64 + nt * 8 + 2 * fcol;
                *(float2*)(s_h + rg * SHL + gc) =
                    make_float2(f2tff(gelu_f(acc[mt][nt].x)), f2tff(gelu_f(acc[mt][nt].y)));
                *(float2*)(s_h + (rg + 8) * SHL + gc) =
                    make_float2(f2tff(gelu_f(acc[mt][nt].z)), f2tff(gelu_f(acc[mt][nt].w)));
            }
        }
    }
    __syncthreads();

    // phase 3: local = h + hid @ lw2 + b2 -> g_local and s_x (fp32)
    {
        float4 acc[2][4];
#pragma unroll
        for (int nt = 0; nt < 4; ++nt) {
            const int gc = ng * 32 + nt * 8 + 2 * fcol;
            const float b0 = lb2[gc], b1v = lb2[gc + 1];
#pragma unroll
            for (int mt = 0; mt < 2; ++mt) acc[mt][nt] = make_float4(b0, b1v, b0, b1v);
        }
#pragma unroll 4
        for (int ks = 0; ks < 32; ++ks) {
            u32 a[2][4];
#pragma unroll
            for (int mt = 0; mt < 2; ++mt)
                ldA_raw<SHL>(s_h + (mg + mt * 16 + frow) * SHL + ks * 8 + fcol, a[mt]);
#pragma unroll
            for (int nt = 0; nt < 4; ++nt) {
                const float2 b = g_w2p[(ks * 16 + ng * 4 + nt) * 32 + lane];
#pragma unroll
                for (int mt = 0; mt < 2; ++mt)
                    mma8(acc[mt][nt], a[mt], __float_as_uint(b.x), __float_as_uint(b.y));
            }
        }
#pragma unroll
        for (int mt = 0; mt < 2; ++mt) {
#pragma unroll
            for (int rr = 0; rr < 2; ++rr) {
                const int tl = mg + mt * 16 + frow + rr * 8;
                const int gt = gt0 + tl;
                const int xt = __ldg(x + gt);
#pragma unroll
                for (int nt = 0; nt < 4; ++nt) {
                    const int gc = ng * 32 + nt * 8 + 2 * fcol;
                    const float2 e = *(const float2*)(emb + xt * Dm + gc);
                    const float2 p = *(const float2*)(pos + (gt & 7) * Dm + gc);
                    const float cx = rr ? acc[mt][nt].z : acc[mt][nt].x;
                    const float cy = rr ? acc[mt][nt].w : acc[mt][nt].y;
                    const float2 o = make_float2(e.x + p.x + cx, e.y + p.y + cy);
                    *(float2*)(g_local + gt * Dm + gc) = o;
                    *(float2*)(s_x + tl * SXL + gc) = o;
                }
            }
        }
    }
    __syncthreads();

    // phase 4: chunk means (8 chunks) -> s_h[0:1024]
#pragma unroll
    for (int it = 0; it < 4; ++it) {
        const int idx = tid + it * 256;
        const int c = idx >> 7, dd = idx & 127;
        float s = 0.f;
#pragma unroll
        for (int t = 0; t < 8; ++t) s += s_x[(c * 8 + t) * SXL + dd];
        s_h[c * 128 + dd] = s * 0.125f;
    }
    __syncthreads();

    // phase 5: summ = mean @ pool_w + pool_b -> g_hA (warp per chunk)
    {
        const int j0 = lane * 4;
        u64 acc1[1][2];
        acc1[0][0] = pk2(pb[j0], pb[j0 + 1]);
        acc1[0][1] = pk2(pb[j0 + 2], pb[j0 + 3]);
        mm_acc<128, 1, 2>(s_h + wid * 128, pw + j0, 128, acc1);
        const float2 v0 = u2f(acc1[0][0]), v1 = u2f(acc1[0][1]);
        *(float4*)(g_hA + (blockIdx.x * 8 + wid) * Dm + j0) =
            make_float4(v0.x, v0.y, v1.x, v1.y);
    }
}

// ============================================================
// K2a: proj = [hmsg @ w1s | hmsg @ w1n] -> g_proj (tensor)
// 32 rows/block, grid 512, 128 threads (4 warps: mat x nh)
// ============================================================
__global__ __launch_bounds__(128) void k_mproj(int useA)
{
    const float* __restrict__ hin = useA ? g_hA : g_hB;
    __shared__ float s_in[32 * SXL];
    const int tid = threadIdx.x, wid = tid >> 5, lane = tid & 31;
    const int r0 = blockIdx.x * 32;
    const int frow = lane >> 2, fcol = lane & 3;

#pragma unroll
    for (int it = 0; it < 32; ++it) {
        const int idx = tid + it * 128;
        const int r = idx >> 7, dd = idx & 127;
        s_in[r * SXL + dd] = f2tff(hin[(r0 + r) * Dm + dd]);
    }
    __syncthreads();

    const int mat = wid >> 1;             // 0=self, 1=nbr
    const int nh = wid & 1;               // col half (64 cols)
    const float2* __restrict__ WP = g_mwp + mat * 8192;

    float4 acc[2][8];
#pragma unroll
    for (int mt = 0; mt < 2; ++mt)
#pragma unroll
        for (int nt = 0; nt < 8; ++nt) acc[mt][nt] = make_float4(0.f, 0.f, 0.f, 0.f);

#pragma unroll 4
    for (int ks = 0; ks < 16; ++ks) {
        u32 a[2][4];
#pragma unroll
        for (int mt = 0; mt < 2; ++mt)
            ldA_raw<SXL>(s_in + (mt * 16 + frow) * SXL + ks * 8 + fcol, a[mt]);
#pragma unroll
        for (int nt = 0; nt < 8; ++nt) {
            const float2 b = WP[(ks * 16 + nh * 8 + nt) * 32 + lane];
#pragma unroll
            for (int mt = 0; mt < 2; ++mt)
                mma8(acc[mt][nt], a[mt], __float_as_uint(b.x), __float_as_uint(b.y));
        }
    }

#pragma unroll
    for (int mt = 0; mt < 2; ++mt) {
        const int rg = r0 + mt * 16 + frow;
#pragma unroll
        for (int nt = 0; nt < 8; ++nt) {
            const int gc = mat * 128 + nh * 64 + nt * 8 + 2 * fcol;
            *(float2*)(g_proj + rg * Hm + gc)       = make_float2(acc[mt][nt].x, acc[mt][nt].y);
            *(float2*)(g_proj + (rg + 8) * Hm + gc) = make_float2(acc[mt][nt].z, acc[mt][nt].w);
        }
    }
}

// ============================================================
// K2b: gelu-sum -> agg -> upd MLP -> LN (-> bc on last round)
// 32 rows/block, grid 512, 128 threads, ~50KB dyn smem, 4 CTAs/SM
// ============================================================
__global__ __launch_bounds__(128, 4) void k_msg2(
    int useA, int last,
    const float* __restrict__ mb1, const float* __restrict__ mb2,
    const float* __restrict__ ub1, const float* __restrict__ ub2,
    const float* __restrict__ lg, const float* __restrict__ lb,
    const float* __restrict__ bcb)
{
    const float* __restrict__ hin = useA ? g_hA : g_hB;
    float* __restrict__ hout = useA ? g_hB : g_hA;
    extern __shared__ float sm[];
    float* s_hm = sm;              // 32x132 fp32 hmsg (last round: tf32 LN result)
    float* s_hs = sm + 32 * SXL;   // 32x132 tf32 gelu-sum, later uh
    float* s_ag = sm + 64 * SXL;   // 32x132 tf32 agg, later fp32 pre-LN
    const int tid = threadIdx.x, wid = tid >> 5, lane = tid & 31;
    const int r0 = blockIdx.x * 32;
    const int frow = lane >> 2, fcol = lane & 3;
    const int ng = wid;            // 4 n-groups of 32 cols

    // P0: load hmsg + gelu-sum from g_proj
#pragma unroll
    for (int it = 0; it < 32; ++it) {
        const int idx = tid + it * 128;
        const int r = idx >> 7, j = idx & 127;
        s_hm[r * SXL + j] = hin[(r0 + r) * Dm + j];
        const int row = r0 + r;
        const int i = row & 1023;
        const float ps_b = __ldg(g_proj + row * Hm + j) + mb1[j];
        float a = 0.f;
#pragma unroll
        for (int dd = 0; dd < 5; ++dd) {
            if (i >= dd) a += gelu_f(ps_b + __ldg(g_proj + (row - dd) * Hm + 128 + j));
        }
        s_hs[r * SXL + j] = f2tff(a);
    }
    __syncthreads();

    // P1: agg = (HS @ mw2)/count + b2 -> s_ag (tf32)
    {
        float4 acc[2][4];
#pragma unroll
        for (int mt = 0; mt < 2; ++mt)
#pragma unroll
            for (int nt = 0; nt < 4; ++nt) acc[mt][nt] = make_float4(0.f, 0.f, 0.f, 0.f);
#pragma unroll 4
        for (int ks = 0; ks < 16; ++ks) {
            u32 a[2][4];
#pragma unroll
            for (int mt = 0; mt < 2; ++mt)
                ldA_raw<SXL>(s_hs + (mt * 16 + frow) * SXL + ks * 8 + fcol, a[mt]);
#pragma unroll
            for (int nt = 0; nt < 4; ++nt) {
                const float2 b = g_mwp[2 * 8192 + (ks * 16 + ng * 4 + nt) * 32 + lane];
#pragma unroll
                for (int mt = 0; mt < 2; ++mt)
                    mma8(acc[mt][nt], a[mt], __float_as_uint(b.x), __float_as_uint(b.y));
            }
        }
        __syncthreads();
#pragma unroll
        for (int mt = 0; mt < 2; ++mt) {
            const int rA = mt * 16 + frow;
            const int iA = (r0 + rA) & 1023, iB = (r0 + rA + 8) & 1023;
            const float invA = 1.0f / ((iA + 1) < 5 ? (float)(iA + 1) : 5.0f);
            const float invB = 1.0f / ((iB + 1) < 5 ? (float)(iB + 1) : 5.0f);
#pragma unroll
            for (int nt = 0; nt < 4; ++nt) {
                const int gc = ng * 32 + nt * 8 + 2 * fcol;
                const float b20 = mb2[gc], b21 = mb2[gc + 1];
                *(float2*)(s_ag + rA * SXL + gc) =
                    make_float2(f2tff(acc[mt][nt].x * invA + b20),
                                f2tff(acc[mt][nt].y * invA + b21));
                *(float2*)(s_ag + (rA + 8) * SXL + gc) =
                    make_float2(f2tff(acc[mt][nt].z * invB + b20),
                                f2tff(acc[mt][nt].w * invB + b21));
            }
        }
    }
    __syncthreads();

    // P2: uh = gelu(HM @ uw1a + AG @ uw1b + ub1) -> s_hs (tf32)
    {
        float4 acc[2][4];
#pragma unroll
        for (int nt = 0; nt < 4; ++nt) {
            const int gc = ng * 32 + nt * 8 + 2 * fcol;
            const float b0 = ub1[gc], b1v = ub1[gc + 1];
#pragma unroll
            for (int mt = 0; mt < 2; ++mt) acc[mt][nt] = make_float4(b0, b1v, b0, b1v);
        }
#pragma unroll 4
        for (int ks = 0; ks < 16; ++ks) {
            u32 a[2][4];
#pragma unroll
            for (int mt = 0; mt < 2; ++mt)
                ldA_cvt<SXL>(s_hm + (mt * 16 + frow) * SXL + ks * 8 + fcol, a[mt]);
#pragma unroll
            for (int nt = 0; nt < 4; ++nt) {
                const float2 b = g_mwp[3 * 8192 + (ks * 16 + ng * 4 + nt) * 32 + lane];
#pragma unroll
                for (int mt = 0; mt < 2; ++mt)
                    mma8(acc[mt][nt], a[mt], __float_as_uint(b.x), __float_as_uint(b.y));
            }
        }
#pragma unroll 4
        for (int ks = 0; ks < 16; ++ks) {
            u32 a[2][4];
#pragma unroll
            for (int mt = 0; mt < 2; ++mt)
                ldA_raw<SXL>(s_ag + (mt * 16 + frow) * SXL + ks * 8 + fcol, a[mt]);
#pragma unroll
            for (int nt = 0; nt < 4; ++nt) {
                const float2 b = g_mwp[4 * 8192 + (ks * 16 + ng * 4 + nt) * 32 + lane];
#pragma unroll
                for (int mt = 0; mt < 2; ++mt)
                    mma8(acc[mt][nt], a[mt], __float_as_uint(b.x), __float_as_uint(b.y));
            }
        }
        __syncthreads();
#pragma unroll
        for (int mt = 0; mt < 2; ++mt) {
            const int rA = mt * 16 + frow;
#pragma unroll
            for (int nt = 0; nt < 4; ++nt) {
                const int gc = ng * 32 + nt * 8 + 2 * fcol;
                *(float2*)(s_hs + rA * SXL + gc) =
                    make_float2(f2tff(gelu_f(acc[mt][nt].x)), f2tff(gelu_f(acc[mt][nt].y)));
                *(float2*)(s_hs + (rA + 8) * SXL + gc) =
                    make_float2(f2tff(gelu_f(acc[mt][nt].z)), f2tff(gelu_f(acc[mt][nt].w)));
            }
        }
    }
    __syncthreads();

    // P3: pre-LN = hmsg + UH @ uw2 + ub2 -> s_ag (fp32)
    {
        float4 acc[2][4];
#pragma unroll
        for (int nt = 0; nt < 4; ++nt) {
            const int gc = ng * 32 + nt * 8 + 2 * fcol;
            const float b0 = ub2[gc], b1v = ub2[gc + 1];
#pragma unroll
            for (int mt = 0; mt < 2; ++mt) acc[mt][nt] = make_float4(b0, b1v, b0, b1v);
        }
#pragma unroll 4
        for (int ks = 0; ks < 16; ++ks) {
            u32 a[2][4];
#pragma unroll
            for (int mt = 0; mt < 2; ++mt)
                ldA_raw<SXL>(s_hs + (mt * 16 + frow) * SXL + ks * 8 + fcol, a[mt]);
#pragma unroll
            for (int nt = 0; nt < 4; ++nt) {
                const float2 b = g_mwp[5 * 8192 + (ks * 16 + ng * 4 + nt) * 32 + lane];
#pragma unroll
                for (int mt = 0; mt < 2; ++mt)
                    mma8(acc[mt][nt], a[mt], __float_as_uint(b.x), __float_as_uint(b.y));
            }
        }
        __syncthreads();
#pragma unroll
        for (int mt = 0; mt < 2; ++mt) {
            const int rA = mt * 16 + frow;
#pragma unroll
            for (int nt = 0; nt < 4; ++nt) {
                const int gc = ng * 32 + nt * 8 + 2 * fcol;
                const float2 h0 = *(const float2*)(s_hm + rA * SXL + gc);
                const float2 h1 = *(const float2*)(s_hm + (rA + 8) * SXL + gc);
                *(float2*)(s_ag + rA * SXL + gc) =
                    make_float2(h0.x + acc[mt][nt].x, h0.y + acc[mt][nt].y);
                *(float2*)(s_ag + (rA + 8) * SXL + gc) =
                    make_float2(h1.x + acc[mt][nt].z, h1.y + acc[mt][nt].w);
            }
        }
    }
    __syncthreads();

    // P4: LN per row (8 rows/warp). Non-final: -> hout. Final: tf32 -> s_hm.
#pragma unroll
    for (int rr = 0; rr < 8; ++rr) {
        const int r = wid * 8 + rr;
        const float4 v0 = *(const float4*)(s_ag + r * SXL + lane * 4);
        const float4 v = ln_f4(v0, lg, lb, lane);
        if (!last) {
            *(float4*)(hout + (r0 + r) * Dm + lane * 4) = v;
        } else {
            float* dst = s_hm + r * SXL + lane * 4;
            dst[0] = f2tff(v.x); dst[1] = f2tff(v.y);
            dst[2] = f2tff(v.z); dst[3] = f2tff(v.w);
        }
    }

    // P5 (final round only): bc = hmsg_final @ bc_w + bc_b -> g_bcb
    if (last) {
        __syncthreads();
        float4 acc[2][4];
#pragma unroll
        for (int nt = 0; nt < 4; ++nt) {
            const int gc = ng * 32 + nt * 8 + 2 * fcol;
            const float b0 = bcb[gc], b1v = bcb[gc + 1];
#pragma unroll
            for (int mt = 0; mt < 2; ++mt) acc[mt][nt] = make_float4(b0, b1v, b0, b1v);
        }
#pragma unroll 4
        for (int ks = 0; ks < 16; ++ks) {
            u32 a[2][4];
#pragma unroll
            for (int mt = 0; mt < 2; ++mt)
                ldA_raw<SXL>(s_hm + (mt * 16 + frow) * SXL + ks * 8 + fcol, a[mt]);
#pragma unroll
            for (int nt = 0; nt < 4; ++nt) {
                const float2 b = g_mwp[6 * 8192 + (ks * 16 + ng * 4 + nt) * 32 + lane];
#pragma unroll
                for (int mt = 0; mt < 2; ++mt)
                    mma8(acc[mt][nt], a[mt], __float_as_uint(b.x), __float_as_uint(b.y));
            }
        }
#pragma unroll
        for (int mt = 0; mt < 2; ++mt) {
            const int rA = r0 + mt * 16 + frow;
#pragma unroll
            for (int nt = 0; nt < 4; ++nt) {
                const int gc = ng * 32 + nt * 8 + 2 * fcol;
                *(float2*)(g_bcb + rA * Dm + gc)       = make_float2(acc[mt][nt].x, acc[mt][nt].y);
                *(float2*)(g_bcb + (rA + 8) * Dm + gc) = make_float2(acc[mt][nt].z, acc[mt][nt].w);
            }
        }
    }
}

// ============================================================
// K5: logits = LN(local + bc) @ head_w (tensor), 64 tok/block
// ============================================================
__global__ __launch_bounds__(256) void k_head(
    const float* __restrict__ lg, const float* __restrict__ lb,
    float* __restrict__ out)
{
    __shared__ float s_x[64 * SXL];
    const int tid = threadIdx.x, wid = tid >> 5, lane = tid & 31;
    const int gt0 = blockIdx.x * 64;
    const int frow = lane >> 2, fcol = lane & 3;

#pragma unroll
    for (int tt = 0; tt < 8; ++tt) {
        const int tl = wid * 8 + tt, gt = gt0 + tl;
        const float4 lv = *(const float4*)(g_local + gt * Dm + lane * 4);
        const float4 bv = *(const float4*)(g_bcb + (gt >> 3) * Dm + lane * 4);
        const float4 h = make_float4(lv.x + bv.x, lv.y + bv.y, lv.z + bv.z, lv.w + bv.w);
        const float4 v = ln_f4(h, lg, lb, lane);
        float* dst = s_x + tl * SXL + lane * 4;
        dst[0] = f2tff(v.x); dst[1] = f2tff(v.y); dst[2] = f2tff(v.z); dst[3] = f2tff(v.w);
    }
    __syncthreads();

    const int mg = (wid >> 2) * 32;
    const int ng = (wid & 3);
    float4 acc[2][8];
#pragma unroll
    for (int mt = 0; mt < 2; ++mt)
#pragma unroll
        for (int nt = 0; nt < 8; ++nt) acc[mt][nt] = make_float4(0.f, 0.f, 0.f, 0.f);

#pragma unroll 4
    for (int ks = 0; ks < 16; ++ks) {
        u32 a[2][4];
#pragma unroll
        for (int mt = 0; mt < 2; ++mt)
            ldA_raw<SXL>(s_x + (mg + mt * 16 + frow) * SXL + ks * 8 + fcol, a[mt]);
#pragma unroll
        for (int nt = 0; nt < 8; ++nt) {
            const float2 b = g_hwp[(ks * 32 + ng * 8 + nt) * 32 + lane];
#pragma unroll
            for (int mt = 0; mt < 2; ++mt)
                mma8(acc[mt][nt], a[mt], __float_as_uint(b.x), __float_as_uint(b.y));
        }
    }

#pragma unroll
    for (int mt = 0; mt < 2; ++mt) {
        const int rg = gt0 + mg + mt * 16 + frow;
#pragma unroll
        for (int nt = 0; nt < 8; ++nt) {
            const int gc = ng * 64 + nt * 8 + 2 * fcol;
            *(float2*)(out + rg * Hm + gc)       = make_float2(acc[mt][nt].x, acc[mt][nt].y);
            *(float2*)(out + (rg + 8) * Hm + gc) = make_float2(acc[mt][nt].z, acc[mt][nt].w);
        }
    }
}

// ============================================================
extern "C" void kernel_launch(void* const* d_in, const int* in_sizes, int n_in,
                              void* d_out, int out_size) {
    const int*   x      = (const int*)  d_in[0];
    const float* emb    = (const float*)d_in[1];
    const float* pos    = (const float*)d_in[2];
    const float* lw1    = (const float*)d_in[3];
    const float* lb1    = (const float*)d_in[4];
    const float* lw2    = (const float*)d_in[5];
    const float* lb2    = (const float*)d_in[6];
    const float* lln_g  = (const float*)d_in[7];
    const float* lln_b  = (const float*)d_in[8];
    const float* pool_w = (const float*)d_in[9];
    const float* pool_b = (const float*)d_in[10];
    const float* msg_w1 = (const float*)d_in[11];
    const float* msg_b1 = (const float*)d_in[12];
    const float* msg_w2 = (const float*)d_in[13];
    const float* msg_b2 = (const float*)d_in[14];
    const float* upd_w1 = (const float*)d_in[15];
    const float* upd_b1 = (const float*)d_in[16];
    const float* upd_w2 = (const float*)d_in[17];
    const float* upd_b2 = (const float*)d_in[18];
    const float* mln_g  = (const float*)d_in[19];
    const float* mln_b  = (const float*)d_in[20];
    const float* bc_w   = (const float*)d_in[21];
    const float* bc_b   = (const float*)d_in[22];
    const float* fln_g  = (const float*)d_in[23];
    const float* fln_b  = (const float*)d_in[24];
    const float* head_w = (const float*)d_in[25];
    float* out = (float*)d_out;

    const int SMEM_LOCAL = (64 * SXL + 64 * SHL) * 4;   // 100352 B
    const int SMEM_MSG   = (96 * SXL) * 4;              // 50688 B
    cudaFuncSetAttribute(k_local, cudaFuncAttributeMaxDynamicSharedMemorySize, SMEM_LOCAL);
    cudaFuncSetAttribute(k_msg2,  cudaFuncAttributeMaxDynamicSharedMemorySize, SMEM_MSG);

    k_pack_all<<<416, 256>>>(lw1, lw2, head_w, msg_w1, msg_w2, upd_w1, upd_w2, bc_w);

    k_local<<<NTOK / 64, 256, SMEM_LOCAL>>>(x, emb, pos, lb1, lb2,
                                            lln_g, lln_b, pool_w, pool_b);

    // rounds: A->B, B->A, A->(bc)  (last round writes g_bcb, skips hout)
    for (int r = 0; r < 3; ++r) {
        const int useA = (r % 2 == 0) ? 1 : 0;
        const int last = (r == 2) ? 1 : 0;
        k_mproj<<<ROWS / 32, 128>>>(useA);
        k_msg2<<<ROWS / 32, 128, SMEM_MSG>>>(useA, last, msg_b1, msg_b2,
                                             upd_b1, upd_b2, mln_g, mln_b, bc_b);
    }

    k_head<<<NTOK / 64, 256>>>(fln_g, fln_b, out);
}